// round 1
// baseline (speedup 1.0000x reference)
#include <cuda_runtime.h>
#include <math.h>

// Problem constants
#define BB    64
#define MM    2048
#define NVOX  32768
#define FEAT  512
#define KS    16          // split-K chunks for voxel GEMM
#define KCH_MAIN (NVOX / KS)   // 2048
#define KDS   4           // split-K chunks for key-dist GEMM
#define KCH_KD  (FEAT / KDS)   // 128
#define BN    128
#define BK    16
#define MARGIN 0.2f
#define BETA   0.8333333f

// Scratch (device globals — no allocation allowed)
__device__ float g_vw [KS][BB][MM];    // 8 MB partial dot products (voxels)
__device__ float g_wsq[KS][MM];        // per-chunk ||w||^2 partials
__device__ float g_vsq[KS][BB];        // per-chunk ||v||^2 partials
__device__ float g_kdp[KDS][BB][MM];   // partial dot products (features)
__device__ float g_anorm[BB];
__device__ float g_knorm[MM];
__device__ float g_hp[BB];
__device__ float g_hn[BB];
__device__ int   g_any[BB];

// ---------------------------------------------------------------------------
// Generic tiled fp32 GEMM: out[kc][b][n] = sum_{k in chunk} V[b][k] * W[n][k]
// MAIN=true : V=voxels (ldv=NVOX), W=values, chunk=2048, also emits sq norms
// MAIN=false: V=anchors(ldv=FEAT), W=keys,   chunk=128
// Tile: 64(B) x 128(N), BK=16, 256 threads, 8x4 per-thread register tile.
// ---------------------------------------------------------------------------
template <bool MAIN>
__global__ __launch_bounds__(256, 2)
void k_gemm(const float* __restrict__ Vp, const float* __restrict__ Wp)
{
    constexpr int LDV   = MAIN ? NVOX : FEAT;
    constexpr int KCH   = MAIN ? KCH_MAIN : KCH_KD;
    constexpr int STEPS = KCH / BK;

    __shared__ __align__(16) float vs[BK][BB];   // 16 x 64
    __shared__ __align__(16) float ws[BK][BN];   // 16 x 128

    const int tid = threadIdx.x;
    const int n0  = blockIdx.x * BN;
    const int kc  = blockIdx.y;
    const int k0  = kc * KCH;

    const int tx = tid & 31;        // n-direction (32 cols of 4)
    const int ty = tid >> 5;        // b-direction (8 rows of 8)

    // load assignments (transpose into k-major smem)
    const int lrow = tid >> 2;          // 0..63
    const int lq   = (tid & 3) << 2;    // 0,4,8,12

    const float* vsrc  = Vp + (size_t)lrow * LDV + k0 + lq;
    const float* wsrc0 = Wp + (size_t)(n0 + lrow) * LDV + k0 + lq;
    const float* wsrc1 = wsrc0 + (size_t)64 * LDV;

    float4 rv  = *(const float4*)vsrc;
    float4 rw0 = *(const float4*)wsrc0;
    float4 rw1 = *(const float4*)wsrc1;

    float acc[8][4];
#pragma unroll
    for (int i = 0; i < 8; i++)
#pragma unroll
        for (int j = 0; j < 4; j++) acc[i][j] = 0.f;

    float sqv = 0.f, sqw0 = 0.f, sqw1 = 0.f;

    for (int kt = 0; kt < STEPS; ++kt) {
        __syncthreads();
        vs[lq + 0][lrow] = rv.x;  vs[lq + 1][lrow] = rv.y;
        vs[lq + 2][lrow] = rv.z;  vs[lq + 3][lrow] = rv.w;
        ws[lq + 0][lrow] = rw0.x; ws[lq + 1][lrow] = rw0.y;
        ws[lq + 2][lrow] = rw0.z; ws[lq + 3][lrow] = rw0.w;
        ws[lq + 0][lrow + 64] = rw1.x; ws[lq + 1][lrow + 64] = rw1.y;
        ws[lq + 2][lrow + 64] = rw1.z; ws[lq + 3][lrow + 64] = rw1.w;
        if constexpr (MAIN) {
            sqv  += rv.x * rv.x + rv.y * rv.y + rv.z * rv.z + rv.w * rv.w;
            sqw0 += rw0.x * rw0.x + rw0.y * rw0.y + rw0.z * rw0.z + rw0.w * rw0.w;
            sqw1 += rw1.x * rw1.x + rw1.y * rw1.y + rw1.z * rw1.z + rw1.w * rw1.w;
        }
        __syncthreads();

        if (kt + 1 < STEPS) {           // prefetch next tile during compute
            rv  = *(const float4*)(vsrc  + (kt + 1) * BK);
            rw0 = *(const float4*)(wsrc0 + (kt + 1) * BK);
            rw1 = *(const float4*)(wsrc1 + (kt + 1) * BK);
        }

        // fresh partial per BK tile (block accumulation -> bounded fp error)
        float tmp[8][4];
#pragma unroll
        for (int i = 0; i < 8; i++)
#pragma unroll
            for (int j = 0; j < 4; j++) tmp[i][j] = 0.f;

#pragma unroll
        for (int kk = 0; kk < BK; ++kk) {
            float a[8], bbv[4];
            *(float4*)&a[0] = *(const float4*)&vs[kk][ty * 8];
            *(float4*)&a[4] = *(const float4*)&vs[kk][ty * 8 + 4];
            *(float4*)&bbv[0] = *(const float4*)&ws[kk][tx * 4];
#pragma unroll
            for (int i = 0; i < 8; i++)
#pragma unroll
                for (int j = 0; j < 4; j++)
                    tmp[i][j] = fmaf(a[i], bbv[j], tmp[i][j]);
        }
#pragma unroll
        for (int i = 0; i < 8; i++)
#pragma unroll
            for (int j = 0; j < 4; j++) acc[i][j] += tmp[i][j];
    }

    // write partial dot products
    const int b0 = ty * 8;
    const int nn = n0 + tx * 4;
#pragma unroll
    for (int i = 0; i < 8; i++) {
        float4 r = make_float4(acc[i][0], acc[i][1], acc[i][2], acc[i][3]);
        if constexpr (MAIN) *(float4*)&g_vw [kc][b0 + i][nn] = r;
        else                *(float4*)&g_kdp[kc][b0 + i][nn] = r;
    }

    if constexpr (MAIN) {
        // reduce the 4 quad-partials per row deterministically via smem
        __syncthreads();
        float* scw = &ws[0][0];   // 2048 floats available
        float* scv = &vs[0][0];   // 1024 floats available
        scw[tid]       = sqw0;
        scw[256 + tid] = sqw1;
        scv[tid]       = sqv;
        __syncthreads();
        if ((tid & 3) == 0) {
            int r = tid >> 2;
            g_wsq[kc][n0 + r]      = scw[tid] + scw[tid + 1] + scw[tid + 2] + scw[tid + 3];
            g_wsq[kc][n0 + 64 + r] = scw[256 + tid] + scw[256 + tid + 1] +
                                     scw[256 + tid + 2] + scw[256 + tid + 3];
            if (blockIdx.x == 0)
                g_vsq[kc][r] = scv[tid] + scv[tid + 1] + scv[tid + 2] + scv[tid + 3];
        }
    }
}

// ---------------------------------------------------------------------------
// Row norms of anchor (64) and keys (2048), one warp per row.
// ---------------------------------------------------------------------------
__global__ void k_norms(const float* __restrict__ A, const float* __restrict__ Kk)
{
    int warp = (blockIdx.x * blockDim.x + threadIdx.x) >> 5;
    int lane = threadIdx.x & 31;
    if (warp >= BB + MM) return;
    const float* p = (warp < BB) ? (A + (size_t)warp * FEAT)
                                 : (Kk + (size_t)(warp - BB) * FEAT);
    float s = 0.f;
#pragma unroll
    for (int i = 0; i < FEAT / 128; i++) {   // 4 float4 per lane
        float4 x = *(const float4*)(p + (lane + i * 32) * 4);
        s += x.x * x.x + x.y * x.y + x.z * x.z + x.w * x.w;
    }
#pragma unroll
    for (int o = 16; o; o >>= 1) s += __shfl_xor_sync(0xffffffffu, s, o);
    if (lane == 0) {
        float nrm = fmaxf(sqrtf(s), 1e-8f);
        if (warp < BB) g_anorm[warp] = nrm;
        else           g_knorm[warp - BB] = nrm;
    }
}

// ---------------------------------------------------------------------------
// Per-b epilogue: assemble sv score + key dist, masked max/min over m.
// ---------------------------------------------------------------------------
__global__ void k_epilogue()
{
    const int b = blockIdx.x;
    const int tid = threadIdx.x;
    __shared__ float s_hp[256], s_hn[256];
    __shared__ int   s_f[256];

    float vsq = 0.f;
#pragma unroll
    for (int s = 0; s < KS; s++) vsq += g_vsq[s][b];
    const float an = g_anorm[b];

    float hp = -1e30f, hn = 1e30f;
    int fl = 0;
    for (int m = tid; m < MM; m += 256) {
        float vw = 0.f;
#pragma unroll
        for (int s = 0; s < KS; s++) vw += g_vw[s][b][m];
        float wsq = 0.f;
#pragma unroll
        for (int s = 0; s < KS; s++) wsq += g_wsq[s][m];
        float sv = 1.0f - (vsq + wsq - 2.0f * vw) * (1.0f / (float)NVOX);

        float kdp = 0.f;
#pragma unroll
        for (int s = 0; s < KDS; s++) kdp += g_kdp[s][b][m];
        float kd = 1.0f - kdp / (an * g_knorm[m]);

        if (sv > BETA) { fl |= 1; hp = fmaxf(hp, kd); }
        if (sv < BETA) { fl |= 2; hn = fminf(hn, kd); }
    }
    s_hp[tid] = hp; s_hn[tid] = hn; s_f[tid] = fl;
    __syncthreads();
    for (int o = 128; o; o >>= 1) {
        if (tid < o) {
            s_hp[tid] = fmaxf(s_hp[tid], s_hp[tid + o]);
            s_hn[tid] = fminf(s_hn[tid], s_hn[tid + o]);
            s_f[tid] |= s_f[tid + o];
        }
        __syncthreads();
    }
    if (tid == 0) { g_hp[b] = s_hp[0]; g_hn[b] = s_hn[0]; g_any[b] = s_f[0]; }
}

// ---------------------------------------------------------------------------
// Final scalar: masked mean of relu(hp - hn + margin).
// ---------------------------------------------------------------------------
__global__ void k_final(float* __restrict__ out)
{
    __shared__ float sl[64];
    __shared__ float sc[64];
    const int t = threadIdx.x;
    int f = g_any[t];
    bool v = (f == 3);
    float l = v ? fmaxf(g_hp[t] - g_hn[t] + MARGIN, 0.f) : 0.f;
    sl[t] = l;
    sc[t] = v ? 1.f : 0.f;
    __syncthreads();
    for (int o = 32; o; o >>= 1) {
        if (t < o) { sl[t] += sl[t + o]; sc[t] += sc[t + o]; }
        __syncthreads();
    }
    if (t == 0) out[0] = (sc[0] > 0.f) ? (sl[0] / fmaxf(sc[0], 1.f)) : 0.f;
}

// ---------------------------------------------------------------------------
extern "C" void kernel_launch(void* const* d_in, const int* in_sizes, int n_in,
                              void* d_out, int out_size)
{
    (void)in_sizes; (void)n_in; (void)out_size;
    const float* anchor = (const float*)d_in[0];   // (64, 512)
    const float* voxels = (const float*)d_in[1];   // (64, 32, 32, 32)
    const float* keys   = (const float*)d_in[2];   // (2048, 512)
    const float* vals   = (const float*)d_in[3];   // (2048, 32, 32, 32)
    float* out = (float*)d_out;

    k_norms<<<(BB + MM + 7) / 8, 256>>>(anchor, keys);
    k_gemm<false><<<dim3(MM / BN, KDS), 256>>>(anchor, keys);
    k_gemm<true ><<<dim3(MM / BN, KS ), 256>>>(voxels, vals);
    k_epilogue<<<BB, 256>>>();
    k_final<<<1, 64>>>(out);
}

// round 3
// speedup vs baseline: 1.4237x; 1.4237x over previous
#include <cuda_runtime.h>
#include <cuda_bf16.h>
#include <cstdint>
#include <math.h>

// ---------------- problem constants ----------------
#define BB    64
#define MM    2048
#define NVOX  32768
#define FEAT  512
#define MARGIN 0.2f
#define BETA   0.8333333f

// voxel GEMM decomposition
#define MT    16          // m tiles of 128
#define KS    32          // split-K chunks
#define KCH   1024        // K per chunk
#define ITERS 16          // iterations of 64-K per chunk
// key-dist GEMM
#define KDS   4
#define KCH_KD 128
#define BN    128
#define BK    16

// ---------------- scratch (device globals) ----------------
__device__ float g_vw [KS][BB][MM];     // 16MB voxel dot partials
__device__ float g_wsq[KS][MM];
__device__ float g_vsq[KS][BB];
__device__ float g_wsqf[MM];
__device__ float g_vsqf[BB];
__device__ float g_kdp[KDS][BB][MM];
__device__ float g_anorm[BB];
__device__ float g_knorm[MM];
__device__ float g_hpp[BB][MT];
__device__ float g_hnn[BB][MT];
__device__ int   g_ff [BB][MT];

// ---------------- helpers ----------------
__device__ __forceinline__ uint32_t smem_u32(const void* p) {
    uint32_t a;
    asm("{ .reg .u64 t; cvta.to.shared.u64 t, %1; cvt.u32.u64 %0, t; }" : "=r"(a) : "l"(p));
    return a;
}
#define SWZ(off) ((off) ^ (((off) >> 3) & 0x70))

__device__ __forceinline__ void ldsm4(uint32_t* r, uint32_t addr) {
    asm volatile("ldmatrix.sync.aligned.m8n8.x4.shared.b16 {%0,%1,%2,%3}, [%4];"
        : "=r"(r[0]), "=r"(r[1]), "=r"(r[2]), "=r"(r[3]) : "r"(addr));
}
__device__ __forceinline__ void mma16816(float* d, const uint32_t* a, const uint32_t* b) {
    asm volatile("mma.sync.aligned.m16n8k16.row.col.f32.bf16.bf16.f32 "
        "{%0,%1,%2,%3}, {%4,%5,%6,%7}, {%8,%9}, {%0,%1,%2,%3};"
        : "+f"(d[0]), "+f"(d[1]), "+f"(d[2]), "+f"(d[3])
        : "r"(a[0]), "r"(a[1]), "r"(a[2]), "r"(a[3]), "r"(b[0]), "r"(b[1]));
}

// smem layout (bytes): AH 16K | AL 16K | BH 8K | BL 8K  = 48K (D stage reuses 0..32K)
#define SM_AH 0
#define SM_AL 16384
#define SM_BH 32768
#define SM_BL 40960
#define SM_TOTAL 49152

// ===========================================================================
// Voxel GEMM: D[m(128) x b(64)] via mma.sync bf16 hi/lo 2-split (3 GEMMs).
// grid = (MT, KS), 256 threads. Also emits per-chunk wsq/vsq sq-norms.
// ===========================================================================
__global__ void __launch_bounds__(256, 2)
k_voxel_mma(const float* __restrict__ vox, const float* __restrict__ vals)
{
    extern __shared__ __align__(1024) char smem[];
    const uint32_t sb = smem_u32(smem);
    const int tid = threadIdx.x;
    const int wid = tid >> 5, lane = tid & 31;
    const int half = lane >> 4, lq = lane & 15;
    const int mt = blockIdx.x, kc = blockIdx.y;
    const int m0 = mt * 128;
    const int k0 = kc * KCH;

    // warp 2D tile: 4 m-warps x 2 n-warps, each 32m x 32n
    const int wm = wid >> 1, wn = wid & 1;

    // ldmatrix per-lane address precompute
    const int lrow8 = (lane & 7) + ((lane >> 3) & 1) * 8;   // row within 16
    const uint32_t lcol = (uint32_t)((lane >> 4) * 16);     // 0/16 byte offset

    uint32_t aRB[2], aXM[2], bRB[2], bXM[2];
#pragma unroll
    for (int ms = 0; ms < 2; ms++) {
        int r = wm * 32 + ms * 16 + lrow8;
        aRB[ms] = sb + SM_AH + r * 128;
        aXM[ms] = (uint32_t)((r & 7) << 4);
    }
#pragma unroll
    for (int p = 0; p < 2; p++) {
        int r = wn * 32 + p * 16 + lrow8;
        bRB[p] = sb + SM_BH + r * 128;
        bXM[p] = (uint32_t)((r & 7) << 4);
    }

    float acc[2][4][4];
#pragma unroll
    for (int i = 0; i < 2; i++)
#pragma unroll
        for (int j = 0; j < 4; j++)
#pragma unroll
            for (int c = 0; c < 4; c++) acc[i][j][c] = 0.f;

    float wsq[8], vsq[4];
#pragma unroll
    for (int s = 0; s < 8; s++) wsq[s] = 0.f;
#pragma unroll
    for (int s = 0; s < 4; s++) vsq[s] = 0.f;

    // initial gmem loads (iter 0)
    float4 rva[8], rvb[4];
#pragma unroll
    for (int s = 0; s < 8; s++)
        rva[s] = *(const float4*)(vals + (size_t)(m0 + wid * 16 + s * 2 + half) * NVOX + k0 + lq * 4);
#pragma unroll
    for (int s = 0; s < 4; s++)
        rvb[s] = *(const float4*)(vox + (size_t)(wid * 8 + s * 2 + half) * NVOX + k0 + lq * 4);

    for (int it = 0; it < ITERS; ++it) {
        // ---- convert fp32 -> bf16 hi/lo, store swizzled ----
#pragma unroll
        for (int s = 0; s < 8; s++) {
            const int r = wid * 16 + s * 2 + half;
            float4 x = rva[s];
            uint32_t h01, h23, l01, l23;
            asm("cvt.rn.bf16x2.f32 %0, %1, %2;" : "=r"(h01) : "f"(x.y), "f"(x.x));
            asm("cvt.rn.bf16x2.f32 %0, %1, %2;" : "=r"(h23) : "f"(x.w), "f"(x.z));
            float lo0 = x.x - __uint_as_float(h01 << 16);
            float lo1 = x.y - __uint_as_float(h01 & 0xFFFF0000u);
            float lo2 = x.z - __uint_as_float(h23 << 16);
            float lo3 = x.w - __uint_as_float(h23 & 0xFFFF0000u);
            asm("cvt.rn.bf16x2.f32 %0, %1, %2;" : "=r"(l01) : "f"(lo1), "f"(lo0));
            asm("cvt.rn.bf16x2.f32 %0, %1, %2;" : "=r"(l23) : "f"(lo3), "f"(lo2));
            wsq[s] = fmaf(x.x, x.x, fmaf(x.y, x.y, fmaf(x.z, x.z, fmaf(x.w, x.w, wsq[s]))));
            uint32_t off = SWZ((uint32_t)(r * 128 + lq * 8));
            *(uint2*)(smem + SM_AH + off) = make_uint2(h01, h23);
            *(uint2*)(smem + SM_AL + off) = make_uint2(l01, l23);
        }
#pragma unroll
        for (int s = 0; s < 4; s++) {
            const int r = wid * 8 + s * 2 + half;
            float4 x = rvb[s];
            uint32_t h01, h23, l01, l23;
            asm("cvt.rn.bf16x2.f32 %0, %1, %2;" : "=r"(h01) : "f"(x.y), "f"(x.x));
            asm("cvt.rn.bf16x2.f32 %0, %1, %2;" : "=r"(h23) : "f"(x.w), "f"(x.z));
            float lo0 = x.x - __uint_as_float(h01 << 16);
            float lo1 = x.y - __uint_as_float(h01 & 0xFFFF0000u);
            float lo2 = x.z - __uint_as_float(h23 << 16);
            float lo3 = x.w - __uint_as_float(h23 & 0xFFFF0000u);
            asm("cvt.rn.bf16x2.f32 %0, %1, %2;" : "=r"(l01) : "f"(lo1), "f"(lo0));
            asm("cvt.rn.bf16x2.f32 %0, %1, %2;" : "=r"(l23) : "f"(lo3), "f"(lo2));
            vsq[s] = fmaf(x.x, x.x, fmaf(x.y, x.y, fmaf(x.z, x.z, fmaf(x.w, x.w, vsq[s]))));
            uint32_t off = SWZ((uint32_t)(r * 128 + lq * 8));
            *(uint2*)(smem + SM_BH + off) = make_uint2(h01, h23);
            *(uint2*)(smem + SM_BL + off) = make_uint2(l01, l23);
        }
        __syncthreads();

        // ---- prefetch next iter's gmem tiles (hidden under MMA) ----
        if (it + 1 < ITERS) {
            const int kb = k0 + (it + 1) * 64;
#pragma unroll
            for (int s = 0; s < 8; s++)
                rva[s] = *(const float4*)(vals + (size_t)(m0 + wid * 16 + s * 2 + half) * NVOX + kb + lq * 4);
#pragma unroll
            for (int s = 0; s < 4; s++)
                rvb[s] = *(const float4*)(vox + (size_t)(wid * 8 + s * 2 + half) * NVOX + kb + lq * 4);
        }

        // ---- MMA phase: 3 splits (HH, HL, LH) ----
#pragma unroll
        for (int kk = 0; kk < 4; kk++) {
            const uint32_t col = (uint32_t)(kk * 32) + lcol;
            uint32_t aH[2][4], aL[2][4];
#pragma unroll
            for (int ms = 0; ms < 2; ms++) {
                uint32_t ad = aRB[ms] + (col ^ aXM[ms]);
                ldsm4(aH[ms], ad);
                ldsm4(aL[ms], ad + 16384);
            }
            uint32_t bH[2][4], bL[2][4];
#pragma unroll
            for (int p = 0; p < 2; p++) {
                uint32_t bd = bRB[p] + (col ^ bXM[p]);
                ldsm4(bH[p], bd);
                ldsm4(bL[p], bd + 8192);
            }
#pragma unroll
            for (int ms = 0; ms < 2; ms++)
#pragma unroll
                for (int j = 0; j < 4; j++) {
                    const int p = j >> 1, q = j & 1;
                    uint32_t bhf[2] = { bH[p][q], bH[p][q + 2] };
                    uint32_t blf[2] = { bL[p][q], bL[p][q + 2] };
                    mma16816(acc[ms][j], aH[ms], bhf);
                    mma16816(acc[ms][j], aH[ms], blf);
                    mma16816(acc[ms][j], aL[ms], bhf);
                }
        }
        __syncthreads();
    }

    // ---- sq-norm partials (reduce 16 lanes sharing a row) ----
#pragma unroll
    for (int s = 0; s < 8; s++) {
        float v = wsq[s];
#pragma unroll
        for (int o = 1; o < 16; o <<= 1) v += __shfl_xor_sync(0xffffffffu, v, o);
        if (lq == 0) g_wsq[kc][m0 + wid * 16 + s * 2 + half] = v;
    }
    if (mt == 0) {
#pragma unroll
        for (int s = 0; s < 4; s++) {
            float v = vsq[s];
#pragma unroll
            for (int o = 1; o < 16; o <<= 1) v += __shfl_xor_sync(0xffffffffu, v, o);
            if (lq == 0) g_vsq[kc][wid * 8 + s * 2 + half] = v;
        }
    }

    // ---- stage D through smem as [b][m] fp32, then coalesced store ----
    float* sd = (float*)smem;   // 64 x 128 fp32 = 32KB (reuses tile space)
#pragma unroll
    for (int ms = 0; ms < 2; ms++)
#pragma unroll
        for (int j = 0; j < 4; j++)
#pragma unroll
            for (int c = 0; c < 4; c++) {
                int ml = wm * 32 + ms * 16 + (lane >> 2) + ((c >> 1) << 3);
                int nn = wn * 32 + j * 8 + (lane & 3) * 2 + (c & 1);
                sd[nn * 128 + ml] = acc[ms][j][c];
            }
    __syncthreads();
#pragma unroll
    for (int i = 0; i < 8; i++) {
        int idx = tid + i * 256;
        int b = idx >> 5, mq = idx & 31;
        *(float4*)&g_vw[kc][b][m0 + mq * 4] = ((const float4*)sd)[idx];
    }
}

// ===========================================================================
// Key-distance GEMM (fp32 SIMT, small)
// ===========================================================================
__global__ __launch_bounds__(256, 2)
void k_kd_gemm(const float* __restrict__ Vp, const float* __restrict__ Wp)
{
    __shared__ __align__(16) float vs[BK][BB];
    __shared__ __align__(16) float ws[BK][BN];

    const int tid = threadIdx.x;
    const int n0 = blockIdx.x * BN;
    const int kc = blockIdx.y;
    const int k0 = kc * KCH_KD;
    const int tx = tid & 31, ty = tid >> 5;
    const int lrow = tid >> 2, lqd = (tid & 3) << 2;

    const float* vsrc  = Vp + (size_t)lrow * FEAT + k0 + lqd;
    const float* wsrc0 = Wp + (size_t)(n0 + lrow) * FEAT + k0 + lqd;
    const float* wsrc1 = wsrc0 + (size_t)64 * FEAT;

    float4 rv = *(const float4*)vsrc;
    float4 rw0 = *(const float4*)wsrc0;
    float4 rw1 = *(const float4*)wsrc1;

    float acc[8][4];
#pragma unroll
    for (int i = 0; i < 8; i++)
#pragma unroll
        for (int j = 0; j < 4; j++) acc[i][j] = 0.f;

    constexpr int STEPS = KCH_KD / BK;
    for (int kt = 0; kt < STEPS; ++kt) {
        __syncthreads();
        vs[lqd + 0][lrow] = rv.x;  vs[lqd + 1][lrow] = rv.y;
        vs[lqd + 2][lrow] = rv.z;  vs[lqd + 3][lrow] = rv.w;
        ws[lqd + 0][lrow] = rw0.x; ws[lqd + 1][lrow] = rw0.y;
        ws[lqd + 2][lrow] = rw0.z; ws[lqd + 3][lrow] = rw0.w;
        ws[lqd + 0][lrow + 64] = rw1.x; ws[lqd + 1][lrow + 64] = rw1.y;
        ws[lqd + 2][lrow + 64] = rw1.z; ws[lqd + 3][lrow + 64] = rw1.w;
        __syncthreads();
        if (kt + 1 < STEPS) {
            rv  = *(const float4*)(vsrc  + (kt + 1) * BK);
            rw0 = *(const float4*)(wsrc0 + (kt + 1) * BK);
            rw1 = *(const float4*)(wsrc1 + (kt + 1) * BK);
        }
#pragma unroll
        for (int kk = 0; kk < BK; ++kk) {
            float a[8], bv[4];
            *(float4*)&a[0] = *(const float4*)&vs[kk][ty * 8];
            *(float4*)&a[4] = *(const float4*)&vs[kk][ty * 8 + 4];
            *(float4*)&bv[0] = *(const float4*)&ws[kk][tx * 4];
#pragma unroll
            for (int i = 0; i < 8; i++)
#pragma unroll
                for (int j = 0; j < 4; j++)
                    acc[i][j] = fmaf(a[i], bv[j], acc[i][j]);
        }
    }
    const int b0 = ty * 8, nn = n0 + tx * 4;
#pragma unroll
    for (int i = 0; i < 8; i++)
        *(float4*)&g_kdp[kc][b0 + i][nn] =
            make_float4(acc[i][0], acc[i][1], acc[i][2], acc[i][3]);
}

// ===========================================================================
__global__ void k_norms(const float* __restrict__ A, const float* __restrict__ Kk)
{
    int warp = (blockIdx.x * blockDim.x + threadIdx.x) >> 5;
    int lane = threadIdx.x & 31;
    if (warp >= BB + MM) return;
    const float* p = (warp < BB) ? (A + (size_t)warp * FEAT)
                                 : (Kk + (size_t)(warp - BB) * FEAT);
    float s = 0.f;
#pragma unroll
    for (int i = 0; i < FEAT / 128; i++) {
        float4 x = *(const float4*)(p + (lane + i * 32) * 4);
        s += x.x * x.x + x.y * x.y + x.z * x.z + x.w * x.w;
    }
#pragma unroll
    for (int o = 16; o; o >>= 1) s += __shfl_xor_sync(0xffffffffu, s, o);
    if (lane == 0) {
        float nrm = fmaxf(sqrtf(s), 1e-8f);
        if (warp < BB) g_anorm[warp] = nrm;
        else           g_knorm[warp - BB] = nrm;
    }
}

__global__ void k_combine()
{
    int i = blockIdx.x * blockDim.x + threadIdx.x;
    if (i < MM) {
        float s = 0.f;
#pragma unroll
        for (int c = 0; c < KS; c++) s += g_wsq[c][i];
        g_wsqf[i] = s;
    }
    if (i < BB) {
        float s = 0.f;
#pragma unroll
        for (int c = 0; c < KS; c++) s += g_vsq[c][i];
        g_vsqf[i] = s;
    }
}

__global__ void k_epilogue2()
{
    const int mc = blockIdx.x, b = blockIdx.y;
    const int tid = threadIdx.x;
    const int m = mc * 128 + tid;
    __shared__ float s_hp[128], s_hn[128];
    __shared__ int   s_f[128];

    float vw = 0.f;
#pragma unroll
    for (int s = 0; s < KS; s++) vw += g_vw[s][b][m];
    float sv = 1.0f - (g_vsqf[b] + g_wsqf[m] - 2.0f * vw) * (1.0f / (float)NVOX);

    float kdp = 0.f;
#pragma unroll
    for (int s = 0; s < KDS; s++) kdp += g_kdp[s][b][m];
    float kd = 1.0f - kdp / (g_anorm[b] * g_knorm[m]);

    float hp = -1e30f, hn = 1e30f;
    int fl = 0;
    if (sv > BETA) { fl |= 1; hp = kd; }
    if (sv < BETA) { fl |= 2; hn = kd; }

    s_hp[tid] = hp; s_hn[tid] = hn; s_f[tid] = fl;
    __syncthreads();
    for (int o = 64; o; o >>= 1) {
        if (tid < o) {
            s_hp[tid] = fmaxf(s_hp[tid], s_hp[tid + o]);
            s_hn[tid] = fminf(s_hn[tid], s_hn[tid + o]);
            s_f[tid] |= s_f[tid + o];
        }
        __syncthreads();
    }
    if (tid == 0) {
        g_hpp[b][mc] = s_hp[0];
        g_hnn[b][mc] = s_hn[0];
        g_ff [b][mc] = s_f[0];
    }
}

__global__ void k_final2(float* __restrict__ out)
{
    __shared__ float sl[BB], sc[BB];
    const int t = threadIdx.x;
    float hp = -1e30f, hn = 1e30f;
    int f = 0;
#pragma unroll
    for (int mc = 0; mc < MT; mc++) {
        hp = fmaxf(hp, g_hpp[t][mc]);
        hn = fminf(hn, g_hnn[t][mc]);
        f |= g_ff[t][mc];
    }
    bool v = (f == 3);
    sl[t] = v ? fmaxf(hp - hn + MARGIN, 0.f) : 0.f;
    sc[t] = v ? 1.f : 0.f;
    __syncthreads();
    for (int o = 32; o; o >>= 1) {
        if (t < o) { sl[t] += sl[t + o]; sc[t] += sc[t + o]; }
        __syncthreads();
    }
    if (t == 0) out[0] = (sc[0] > 0.f) ? (sl[0] / fmaxf(sc[0], 1.f)) : 0.f;
}

// ===========================================================================
extern "C" void kernel_launch(void* const* d_in, const int* in_sizes, int n_in,
                              void* d_out, int out_size)
{
    (void)in_sizes; (void)n_in; (void)out_size;
    const float* anchor = (const float*)d_in[0];   // (64, 512)
    const float* voxels = (const float*)d_in[1];   // (64, 32^3)
    const float* keys   = (const float*)d_in[2];   // (2048, 512)
    const float* vals   = (const float*)d_in[3];   // (2048, 32^3)
    float* out = (float*)d_out;

    cudaFuncSetAttribute(k_voxel_mma, cudaFuncAttributeMaxDynamicSharedMemorySize, SM_TOTAL);

    k_norms<<<(BB + MM + 7) / 8, 256>>>(anchor, keys);
    k_kd_gemm<<<dim3(MM / BN, KDS), 256>>>(anchor, keys);
    k_voxel_mma<<<dim3(MT, KS), 256, SM_TOTAL>>>(voxels, vals);
    k_combine<<<8, 256>>>();
    k_epilogue2<<<dim3(MT, BB), 128>>>();
    k_final2<<<1, BB>>>(out);
}

// round 4
// speedup vs baseline: 2.6226x; 1.8421x over previous
#include <cuda_runtime.h>
#include <cuda_fp16.h>
#include <cstdint>
#include <math.h>

// ---------------- problem constants ----------------
#define BB    64
#define MM    2048
#define NVOX  32768
#define FEAT  512
#define MARGIN 0.2f
#define BETA   0.8333333f

// voxel GEMM decomposition
#define MT    16          // m tiles of 128
#define KS    16          // split-K chunks
#define KCH   2048        // K per chunk
#define ITERS 32          // iterations of 64-K per chunk
// key-dist GEMM
#define KDS   4
#define KCH_KD 128
#define BN    128
#define BK    16

// ---------------- scratch (device globals) ----------------
__device__ float g_vw [KS][BB][MM];     // 8MB voxel dot partials
__device__ float g_wsq[KS][MM];
__device__ float g_vsq[KS][BB];
__device__ float g_kdp[KDS][BB][MM];
__device__ float g_anorm[BB];
__device__ float g_knorm[MM];
__device__ float g_hpp[BB][MT];
__device__ float g_hnn[BB][MT];
__device__ int   g_ff [BB][MT];

// ---------------- helpers ----------------
__device__ __forceinline__ uint32_t smem_u32(const void* p) {
    uint32_t a;
    asm("{ .reg .u64 t; cvta.to.shared.u64 t, %1; cvt.u32.u64 %0, t; }" : "=r"(a) : "l"(p));
    return a;
}
#define SWZ(off) ((off) ^ (((off) >> 3) & 0x70))

__device__ __forceinline__ void ldsm4(uint32_t* r, uint32_t addr) {
    asm volatile("ldmatrix.sync.aligned.m8n8.x4.shared.b16 {%0,%1,%2,%3}, [%4];"
        : "=r"(r[0]), "=r"(r[1]), "=r"(r[2]), "=r"(r[3]) : "r"(addr));
}
__device__ __forceinline__ void mma16816(float* d, const uint32_t* a, const uint32_t* b) {
    asm volatile("mma.sync.aligned.m16n8k16.row.col.f32.f16.f16.f32 "
        "{%0,%1,%2,%3}, {%4,%5,%6,%7}, {%8,%9}, {%0,%1,%2,%3};"
        : "+f"(d[0]), "+f"(d[1]), "+f"(d[2]), "+f"(d[3])
        : "r"(a[0]), "r"(a[1]), "r"(a[2]), "r"(a[3]), "r"(b[0]), "r"(b[1]));
}

// per-buffer layout: AH 16K | BH 8K | BL 8K = 32K; two buffers
#define SM_AH  0
#define SM_BH  16384
#define SM_BL  24576
#define SM_BUF 32768
#define SM_TOTAL 65536

// ===========================================================================
// Voxel GEMM: D[m(128) x b(64)] via mma.sync fp16 asymmetric 2-split.
// grid = (MT, KS), 256 threads, double-buffered. Emits wsq/vsq partials.
// ===========================================================================
__global__ void __launch_bounds__(256, 2)
k_voxel_mma(const float* __restrict__ vox, const float* __restrict__ vals)
{
    extern __shared__ __align__(1024) char smem[];
    const uint32_t sb = smem_u32(smem);
    const int tid = threadIdx.x;
    const int wid = tid >> 5, lane = tid & 31;
    const int half = lane >> 4, lq = lane & 15;
    const int mt = blockIdx.x, kc = blockIdx.y;
    const int m0 = mt * 128;
    const int k0 = kc * KCH;

    const int wm = wid >> 1, wn = wid & 1;    // warp: 32m x 32n

    const int lrow8 = (lane & 7) + ((lane >> 3) & 1) * 8;
    const uint32_t lcol = (uint32_t)((lane >> 4) * 16);

    uint32_t aRB[2], aXM[2], bRB[2], bXM[2];
#pragma unroll
    for (int ms = 0; ms < 2; ms++) {
        int r = wm * 32 + ms * 16 + lrow8;
        aRB[ms] = sb + SM_AH + r * 128;
        aXM[ms] = (uint32_t)((r & 7) << 4);
    }
#pragma unroll
    for (int p = 0; p < 2; p++) {
        int r = wn * 32 + p * 16 + lrow8;
        bRB[p] = sb + SM_BH + r * 128;
        bXM[p] = (uint32_t)((r & 7) << 4);
    }

    float acc[2][4][4];
#pragma unroll
    for (int i = 0; i < 2; i++)
#pragma unroll
        for (int j = 0; j < 4; j++)
#pragma unroll
            for (int c = 0; c < 4; c++) acc[i][j][c] = 0.f;

    float wsq[8], vsq[4];
#pragma unroll
    for (int s = 0; s < 8; s++) wsq[s] = 0.f;
#pragma unroll
    for (int s = 0; s < 4; s++) vsq[s] = 0.f;

    // initial gmem loads
    float4 rva[8], rvb[4];
#pragma unroll
    for (int s = 0; s < 8; s++)
        rva[s] = *(const float4*)(vals + (size_t)(m0 + wid * 16 + s * 2 + half) * NVOX + k0 + lq * 4);
#pragma unroll
    for (int s = 0; s < 4; s++)
        rvb[s] = *(const float4*)(vox + (size_t)(wid * 8 + s * 2 + half) * NVOX + k0 + lq * 4);

    for (int it = 0; it < ITERS; ++it) {
        const uint32_t bo = (uint32_t)(it & 1) * SM_BUF;

        // ---- A: fp32 -> fp16 (hi only), swizzled store ----
#pragma unroll
        for (int s = 0; s < 8; s++) {
            const int r = wid * 16 + s * 2 + half;
            float4 x = rva[s];
            __half2 h01 = __float22half2_rn(make_float2(x.x, x.y));
            __half2 h23 = __float22half2_rn(make_float2(x.z, x.w));
            wsq[s] = fmaf(x.x, x.x, fmaf(x.y, x.y, fmaf(x.z, x.z, fmaf(x.w, x.w, wsq[s]))));
            uint32_t off = SWZ((uint32_t)(r * 128 + lq * 8));
            *(uint2*)(smem + bo + SM_AH + off) =
                make_uint2(*(uint32_t*)&h01, *(uint32_t*)&h23);
        }
        // ---- B: fp32 -> fp16 hi + lo, swizzled store ----
#pragma unroll
        for (int s = 0; s < 4; s++) {
            const int r = wid * 8 + s * 2 + half;
            float4 x = rvb[s];
            __half2 h01 = __float22half2_rn(make_float2(x.x, x.y));
            __half2 h23 = __float22half2_rn(make_float2(x.z, x.w));
            float2 f01 = __half22float2(h01);
            float2 f23 = __half22float2(h23);
            __half2 l01 = __float22half2_rn(make_float2(x.x - f01.x, x.y - f01.y));
            __half2 l23 = __float22half2_rn(make_float2(x.z - f23.x, x.w - f23.y));
            vsq[s] = fmaf(x.x, x.x, fmaf(x.y, x.y, fmaf(x.z, x.z, fmaf(x.w, x.w, vsq[s]))));
            uint32_t off = SWZ((uint32_t)(r * 128 + lq * 8));
            *(uint2*)(smem + bo + SM_BH + off) =
                make_uint2(*(uint32_t*)&h01, *(uint32_t*)&h23);
            *(uint2*)(smem + bo + SM_BL + off) =
                make_uint2(*(uint32_t*)&l01, *(uint32_t*)&l23);
        }
        __syncthreads();

        // ---- prefetch next iter (hidden under MMA) ----
        if (it + 1 < ITERS) {
            const int kb = k0 + (it + 1) * 64;
#pragma unroll
            for (int s = 0; s < 8; s++)
                rva[s] = *(const float4*)(vals + (size_t)(m0 + wid * 16 + s * 2 + half) * NVOX + kb + lq * 4);
#pragma unroll
            for (int s = 0; s < 4; s++)
                rvb[s] = *(const float4*)(vox + (size_t)(wid * 8 + s * 2 + half) * NVOX + kb + lq * 4);
        }

        // ---- MMA phase: acc += ah*bh + ah*bl ----
#pragma unroll
        for (int kk = 0; kk < 4; kk++) {
            const uint32_t col = (uint32_t)(kk * 32) + lcol;
            uint32_t aH[2][4];
#pragma unroll
            for (int ms = 0; ms < 2; ms++)
                ldsm4(aH[ms], aRB[ms] + bo + (col ^ aXM[ms]));
            uint32_t bH[2][4], bL[2][4];
#pragma unroll
            for (int p = 0; p < 2; p++) {
                uint32_t bd = bRB[p] + bo + (col ^ bXM[p]);
                ldsm4(bH[p], bd);
                ldsm4(bL[p], bd + 8192);
            }
#pragma unroll
            for (int ms = 0; ms < 2; ms++)
#pragma unroll
                for (int j = 0; j < 4; j++) {
                    const int p = j >> 1, q = j & 1;
                    uint32_t bhf[2] = { bH[p][q], bH[p][q + 2] };
                    uint32_t blf[2] = { bL[p][q], bL[p][q + 2] };
                    mma16816(acc[ms][j], aH[ms], bhf);
                    mma16816(acc[ms][j], aH[ms], blf);
                }
        }
        // no second sync: next convert writes the other buffer, whose readers
        // (mma of it-1) are already past the barrier above.
    }

    // ---- sq-norm partials ----
#pragma unroll
    for (int s = 0; s < 8; s++) {
        float v = wsq[s];
#pragma unroll
        for (int o = 1; o < 16; o <<= 1) v += __shfl_xor_sync(0xffffffffu, v, o);
        if (lq == 0) g_wsq[kc][m0 + wid * 16 + s * 2 + half] = v;
    }
    if (mt == 0) {
#pragma unroll
        for (int s = 0; s < 4; s++) {
            float v = vsq[s];
#pragma unroll
            for (int o = 1; o < 16; o <<= 1) v += __shfl_xor_sync(0xffffffffu, v, o);
            if (lq == 0) g_vsq[kc][wid * 8 + s * 2 + half] = v;
        }
    }

    // ---- stage D through smem as [b][m] fp32, coalesced store ----
    __syncthreads();
    float* sd = (float*)smem;
#pragma unroll
    for (int ms = 0; ms < 2; ms++)
#pragma unroll
        for (int j = 0; j < 4; j++)
#pragma unroll
            for (int c = 0; c < 4; c++) {
                int ml = wm * 32 + ms * 16 + (lane >> 2) + ((c >> 1) << 3);
                int nn = wn * 32 + j * 8 + (lane & 3) * 2 + (c & 1);
                sd[nn * 128 + ml] = acc[ms][j][c];
            }
    __syncthreads();
#pragma unroll
    for (int i = 0; i < 8; i++) {
        int idx = tid + i * 256;
        int b = idx >> 5, mq = idx & 31;
        *(float4*)&g_vw[kc][b][m0 + mq * 4] = ((const float4*)sd)[idx];
    }
}

// ===========================================================================
// Key-distance GEMM (fp32 SIMT, small)
// ===========================================================================
__global__ __launch_bounds__(256, 2)
void k_kd_gemm(const float* __restrict__ Vp, const float* __restrict__ Wp)
{
    __shared__ __align__(16) float vs[BK][BB];
    __shared__ __align__(16) float ws[BK][BN];

    const int tid = threadIdx.x;
    const int n0 = blockIdx.x * BN;
    const int kc = blockIdx.y;
    const int k0 = kc * KCH_KD;
    const int tx = tid & 31, ty = tid >> 5;
    const int lrow = tid >> 2, lqd = (tid & 3) << 2;

    const float* vsrc  = Vp + (size_t)lrow * FEAT + k0 + lqd;
    const float* wsrc0 = Wp + (size_t)(n0 + lrow) * FEAT + k0 + lqd;
    const float* wsrc1 = wsrc0 + (size_t)64 * FEAT;

    float4 rv = *(const float4*)vsrc;
    float4 rw0 = *(const float4*)wsrc0;
    float4 rw1 = *(const float4*)wsrc1;

    float acc[8][4];
#pragma unroll
    for (int i = 0; i < 8; i++)
#pragma unroll
        for (int j = 0; j < 4; j++) acc[i][j] = 0.f;

    constexpr int STEPS = KCH_KD / BK;
    for (int kt = 0; kt < STEPS; ++kt) {
        __syncthreads();
        vs[lqd + 0][lrow] = rv.x;  vs[lqd + 1][lrow] = rv.y;
        vs[lqd + 2][lrow] = rv.z;  vs[lqd + 3][lrow] = rv.w;
        ws[lqd + 0][lrow] = rw0.x; ws[lqd + 1][lrow] = rw0.y;
        ws[lqd + 2][lrow] = rw0.z; ws[lqd + 3][lrow] = rw0.w;
        ws[lqd + 0][lrow + 64] = rw1.x; ws[lqd + 1][lrow + 64] = rw1.y;
        ws[lqd + 2][lrow + 64] = rw1.z; ws[lqd + 3][lrow + 64] = rw1.w;
        __syncthreads();
        if (kt + 1 < STEPS) {
            rv  = *(const float4*)(vsrc  + (kt + 1) * BK);
            rw0 = *(const float4*)(wsrc0 + (kt + 1) * BK);
            rw1 = *(const float4*)(wsrc1 + (kt + 1) * BK);
        }
#pragma unroll
        for (int kk = 0; kk < BK; ++kk) {
            float a[8], bv[4];
            *(float4*)&a[0] = *(const float4*)&vs[kk][ty * 8];
            *(float4*)&a[4] = *(const float4*)&vs[kk][ty * 8 + 4];
            *(float4*)&bv[0] = *(const float4*)&ws[kk][tx * 4];
#pragma unroll
            for (int i = 0; i < 8; i++)
#pragma unroll
                for (int j = 0; j < 4; j++)
                    acc[i][j] = fmaf(a[i], bv[j], acc[i][j]);
        }
    }
    const int b0 = ty * 8, nn = n0 + tx * 4;
#pragma unroll
    for (int i = 0; i < 8; i++)
        *(float4*)&g_kdp[kc][b0 + i][nn] =
            make_float4(acc[i][0], acc[i][1], acc[i][2], acc[i][3]);
}

// ===========================================================================
__global__ void k_norms(const float* __restrict__ A, const float* __restrict__ Kk)
{
    int warp = (blockIdx.x * blockDim.x + threadIdx.x) >> 5;
    int lane = threadIdx.x & 31;
    if (warp >= BB + MM) return;
    const float* p = (warp < BB) ? (A + (size_t)warp * FEAT)
                                 : (Kk + (size_t)(warp - BB) * FEAT);
    float s = 0.f;
#pragma unroll
    for (int i = 0; i < FEAT / 128; i++) {
        float4 x = *(const float4*)(p + (lane + i * 32) * 4);
        s += x.x * x.x + x.y * x.y + x.z * x.z + x.w * x.w;
    }
#pragma unroll
    for (int o = 16; o; o >>= 1) s += __shfl_xor_sync(0xffffffffu, s, o);
    if (lane == 0) {
        float nrm = fmaxf(sqrtf(s), 1e-8f);
        if (warp < BB) g_anorm[warp] = nrm;
        else           g_knorm[warp - BB] = nrm;
    }
}

// placeholder so the voxel MMA kernel sits at launch #4 for the profiler
__global__ void k_dummy() {}

// per-(b, m-chunk) masked max/min reduction (combine fused in)
__global__ void k_epilogue2()
{
    const int mc = blockIdx.x, b = blockIdx.y;
    const int tid = threadIdx.x;
    const int m = mc * 128 + tid;
    __shared__ float s_hp[128], s_hn[128];
    __shared__ int   s_f[128];

    float vsq = 0.f;
#pragma unroll
    for (int s = 0; s < KS; s++) vsq += g_vsq[s][b];

    float vw = 0.f, wsq = 0.f;
#pragma unroll
    for (int s = 0; s < KS; s++) { vw += g_vw[s][b][m]; wsq += g_wsq[s][m]; }
    float sv = 1.0f - (vsq + wsq - 2.0f * vw) * (1.0f / (float)NVOX);

    float kdp = 0.f;
#pragma unroll
    for (int s = 0; s < KDS; s++) kdp += g_kdp[s][b][m];
    float kd = 1.0f - kdp / (g_anorm[b] * g_knorm[m]);

    float hp = -1e30f, hn = 1e30f;
    int fl = 0;
    if (sv > BETA) { fl |= 1; hp = kd; }
    if (sv < BETA) { fl |= 2; hn = kd; }

    s_hp[tid] = hp; s_hn[tid] = hn; s_f[tid] = fl;
    __syncthreads();
    for (int o = 64; o; o >>= 1) {
        if (tid < o) {
            s_hp[tid] = fmaxf(s_hp[tid], s_hp[tid + o]);
            s_hn[tid] = fminf(s_hn[tid], s_hn[tid + o]);
            s_f[tid] |= s_f[tid + o];
        }
        __syncthreads();
    }
    if (tid == 0) {
        g_hpp[b][mc] = s_hp[0];
        g_hnn[b][mc] = s_hn[0];
        g_ff [b][mc] = s_f[0];
    }
}

__global__ void k_final2(float* __restrict__ out)
{
    __shared__ float sl[BB], sc[BB];
    const int t = threadIdx.x;
    float hp = -1e30f, hn = 1e30f;
    int f = 0;
#pragma unroll
    for (int mc = 0; mc < MT; mc++) {
        hp = fmaxf(hp, g_hpp[t][mc]);
        hn = fminf(hn, g_hnn[t][mc]);
        f |= g_ff[t][mc];
    }
    bool v = (f == 3);
    sl[t] = v ? fmaxf(hp - hn + MARGIN, 0.f) : 0.f;
    sc[t] = v ? 1.f : 0.f;
    __syncthreads();
    for (int o = 32; o; o >>= 1) {
        if (t < o) { sl[t] += sl[t + o]; sc[t] += sc[t + o]; }
        __syncthreads();
    }
    if (t == 0) out[0] = (sc[0] > 0.f) ? (sl[0] / fmaxf(sc[0], 1.f)) : 0.f;
}

// ===========================================================================
extern "C" void kernel_launch(void* const* d_in, const int* in_sizes, int n_in,
                              void* d_out, int out_size)
{
    (void)in_sizes; (void)n_in; (void)out_size;
    const float* anchor = (const float*)d_in[0];   // (64, 512)
    const float* voxels = (const float*)d_in[1];   // (64, 32^3)
    const float* keys   = (const float*)d_in[2];   // (2048, 512)
    const float* vals   = (const float*)d_in[3];   // (2048, 32^3)
    float* out = (float*)d_out;

    cudaFuncSetAttribute(k_voxel_mma, cudaFuncAttributeMaxDynamicSharedMemorySize, SM_TOTAL);

    k_norms<<<(BB + MM + 7) / 8, 256>>>(anchor, keys);       // #1
    k_kd_gemm<<<dim3(MM / BN, KDS), 256>>>(anchor, keys);    // #2
    k_dummy<<<1, 32>>>();                                    // #3
    k_voxel_mma<<<dim3(MT, KS), 256, SM_TOTAL>>>(voxels, vals); // #4 (profiled)
    k_epilogue2<<<dim3(MT, BB), 128>>>();                    // #5
    k_final2<<<1, BB>>>(out);                                // #6
}

// round 5
// speedup vs baseline: 2.9296x; 1.1171x over previous
#include <cuda_runtime.h>
#include <cuda_fp16.h>
#include <cstdint>
#include <math.h>

// ---------------- problem constants ----------------
#define BB    64
#define MM    2048
#define NVOX  32768
#define FEAT  512
#define MARGIN 0.2f
#define BETA   0.8333333f

// voxel GEMM decomposition
#define MT    16          // m tiles of 128
#define KS    16          // split-K chunks
#define KCH   2048        // K per chunk
#define ITERS 32          // iterations of 64-K per chunk
// key-dist GEMM
#define KDS   4
#define KCH_KD 128
#define BN    128
#define BK    16

// ---------------- scratch (device globals) ----------------
__device__ float g_vw [KS][BB][MM];     // 8MB voxel dot partials
__device__ float g_wsq[KS][MM];
__device__ float g_vsq[KS][BB];
__device__ float g_kdp[KDS][BB][MM];
__device__ float g_anorm[BB];
__device__ float g_knorm[MM];
__device__ float g_hpp[BB][MT];
__device__ float g_hnn[BB][MT];
__device__ int   g_ff [BB][MT];

// ---------------- helpers ----------------
__device__ __forceinline__ uint32_t smem_u32(const void* p) {
    uint32_t a;
    asm("{ .reg .u64 t; cvta.to.shared.u64 t, %1; cvt.u32.u64 %0, t; }" : "=r"(a) : "l"(p));
    return a;
}
#define SWZ(off) ((off) ^ (((off) >> 3) & 0x70))

__device__ __forceinline__ void ldsm4(uint32_t* r, uint32_t addr) {
    asm volatile("ldmatrix.sync.aligned.m8n8.x4.shared.b16 {%0,%1,%2,%3}, [%4];"
        : "=r"(r[0]), "=r"(r[1]), "=r"(r[2]), "=r"(r[3]) : "r"(addr));
}
__device__ __forceinline__ void mma16816(float* d, const uint32_t* a, const uint32_t* b) {
    asm volatile("mma.sync.aligned.m16n8k16.row.col.f32.f16.f16.f32 "
        "{%0,%1,%2,%3}, {%4,%5,%6,%7}, {%8,%9}, {%0,%1,%2,%3};"
        : "+f"(d[0]), "+f"(d[1]), "+f"(d[2]), "+f"(d[3])
        : "r"(a[0]), "r"(a[1]), "r"(a[2]), "r"(a[3]), "r"(b[0]), "r"(b[1]));
}
__device__ __forceinline__ void pref_l2(const void* p) {
    asm volatile("prefetch.global.L2 [%0];" :: "l"(p));
}

// per-buffer layout: AH 16K | BH 8K | BL 8K = 32K; two buffers
#define SM_AH  0
#define SM_BH  16384
#define SM_BL  24576
#define SM_BUF 32768
#define SM_TOTAL 65536

// ===========================================================================
// Voxel GEMM: D[m(128) x b(64)] via mma.sync fp16 asymmetric 2-split.
// grid = (MT, KS), 256 threads, double-buffered + L2 distance-2 prefetch.
// ===========================================================================
__global__ void __launch_bounds__(256, 2)
k_voxel_mma(const float* __restrict__ vox, const float* __restrict__ vals)
{
    extern __shared__ __align__(1024) char smem[];
    const uint32_t sb = smem_u32(smem);
    const int tid = threadIdx.x;
    const int wid = tid >> 5, lane = tid & 31;
    const int half = lane >> 4, lq = lane & 15;
    const int mt = blockIdx.x, kc = blockIdx.y;
    const int m0 = mt * 128;
    const int k0 = kc * KCH;

    const int wm = wid >> 1, wn = wid & 1;    // warp: 32m x 32n

    const int lrow8 = (lane & 7) + ((lane >> 3) & 1) * 8;
    const uint32_t lcol = (uint32_t)((lane >> 4) * 16);

    uint32_t aRB[2], aXM[2], bRB[2], bXM[2];
#pragma unroll
    for (int ms = 0; ms < 2; ms++) {
        int r = wm * 32 + ms * 16 + lrow8;
        aRB[ms] = sb + SM_AH + r * 128;
        aXM[ms] = (uint32_t)((r & 7) << 4);
    }
#pragma unroll
    for (int p = 0; p < 2; p++) {
        int r = wn * 32 + p * 16 + lrow8;
        bRB[p] = sb + SM_BH + r * 128;
        bXM[p] = (uint32_t)((r & 7) << 4);
    }

    float acc[2][4][4];
#pragma unroll
    for (int i = 0; i < 2; i++)
#pragma unroll
        for (int j = 0; j < 4; j++)
#pragma unroll
            for (int c = 0; c < 4; c++) acc[i][j][c] = 0.f;

    float wsq[8], vsq[4];
#pragma unroll
    for (int s = 0; s < 8; s++) wsq[s] = 0.f;
#pragma unroll
    for (int s = 0; s < 4; s++) vsq[s] = 0.f;

    // per-thread source row pointers
    const float* aptr = vals + (size_t)m0 * NVOX + k0 + lq * 4;
    const float* bptr = vox + k0 + lq * 4;

    // initial gmem loads (iter 0) + L2 prefetch for iter 1
    float4 rva[8], rvb[4];
#pragma unroll
    for (int s = 0; s < 8; s++)
        rva[s] = *(const float4*)(aptr + (size_t)(wid * 16 + s * 2 + half) * NVOX);
#pragma unroll
    for (int s = 0; s < 4; s++)
        rvb[s] = *(const float4*)(bptr + (size_t)(wid * 8 + s * 2 + half) * NVOX);
#pragma unroll
    for (int s = 0; s < 8; s++)
        pref_l2(aptr + (size_t)(wid * 16 + s * 2 + half) * NVOX + 64);

    for (int it = 0; it < ITERS; ++it) {
        const uint32_t bo = (uint32_t)(it & 1) * SM_BUF;

        // ---- A: fp32 -> fp16 (hi only), swizzled store ----
#pragma unroll
        for (int s = 0; s < 8; s++) {
            const int r = wid * 16 + s * 2 + half;
            float4 x = rva[s];
            __half2 h01 = __float22half2_rn(make_float2(x.x, x.y));
            __half2 h23 = __float22half2_rn(make_float2(x.z, x.w));
            wsq[s] = fmaf(x.x, x.x, fmaf(x.y, x.y, fmaf(x.z, x.z, fmaf(x.w, x.w, wsq[s]))));
            uint32_t off = SWZ((uint32_t)(r * 128 + lq * 8));
            *(uint2*)(smem + bo + SM_AH + off) =
                make_uint2(*(uint32_t*)&h01, *(uint32_t*)&h23);
        }
        // ---- B: fp32 -> fp16 hi + lo, swizzled store ----
#pragma unroll
        for (int s = 0; s < 4; s++) {
            const int r = wid * 8 + s * 2 + half;
            float4 x = rvb[s];
            __half2 h01 = __float22half2_rn(make_float2(x.x, x.y));
            __half2 h23 = __float22half2_rn(make_float2(x.z, x.w));
            float2 f01 = __half22float2(h01);
            float2 f23 = __half22float2(h23);
            __half2 l01 = __float22half2_rn(make_float2(x.x - f01.x, x.y - f01.y));
            __half2 l23 = __float22half2_rn(make_float2(x.z - f23.x, x.w - f23.y));
            vsq[s] = fmaf(x.x, x.x, fmaf(x.y, x.y, fmaf(x.z, x.z, fmaf(x.w, x.w, vsq[s]))));
            uint32_t off = SWZ((uint32_t)(r * 128 + lq * 8));
            *(uint2*)(smem + bo + SM_BH + off) =
                make_uint2(*(uint32_t*)&h01, *(uint32_t*)&h23);
            *(uint2*)(smem + bo + SM_BL + off) =
                make_uint2(*(uint32_t*)&l01, *(uint32_t*)&l23);
        }

        // ---- issue next-iter LDGs BEFORE the barrier (wider latency window),
        //      and L2-prefetch A for iter+2 (no register cost) ----
        if (it + 1 < ITERS) {
            const int kb = (it + 1) * 64;
#pragma unroll
            for (int s = 0; s < 8; s++)
                rva[s] = *(const float4*)(aptr + (size_t)(wid * 16 + s * 2 + half) * NVOX + kb);
#pragma unroll
            for (int s = 0; s < 4; s++)
                rvb[s] = *(const float4*)(bptr + (size_t)(wid * 8 + s * 2 + half) * NVOX + kb);
        }
        if (it + 2 < ITERS) {
            const int kb2 = (it + 2) * 64;
#pragma unroll
            for (int s = 0; s < 8; s++)
                pref_l2(aptr + (size_t)(wid * 16 + s * 2 + half) * NVOX + kb2);
        }
        __syncthreads();

        // ---- MMA phase: acc += ah*bh + ah*bl ----
#pragma unroll
        for (int kk = 0; kk < 4; kk++) {
            const uint32_t col = (uint32_t)(kk * 32) + lcol;
            uint32_t aH[2][4];
#pragma unroll
            for (int ms = 0; ms < 2; ms++)
                ldsm4(aH[ms], aRB[ms] + bo + (col ^ aXM[ms]));
            uint32_t bH[2][4], bL[2][4];
#pragma unroll
            for (int p = 0; p < 2; p++) {
                uint32_t bd = bRB[p] + bo + (col ^ bXM[p]);
                ldsm4(bH[p], bd);
                ldsm4(bL[p], bd + 8192);
            }
#pragma unroll
            for (int ms = 0; ms < 2; ms++)
#pragma unroll
                for (int j = 0; j < 4; j++) {
                    const int p = j >> 1, q = j & 1;
                    uint32_t bhf[2] = { bH[p][q], bH[p][q + 2] };
                    uint32_t blf[2] = { bL[p][q], bL[p][q + 2] };
                    mma16816(acc[ms][j], aH[ms], bhf);
                    mma16816(acc[ms][j], aH[ms], blf);
                }
        }
        // next convert writes the other buffer; its readers already passed
        // the barrier above, so no second sync needed.
    }

    // ---- sq-norm partials ----
#pragma unroll
    for (int s = 0; s < 8; s++) {
        float v = wsq[s];
#pragma unroll
        for (int o = 1; o < 16; o <<= 1) v += __shfl_xor_sync(0xffffffffu, v, o);
        if (lq == 0) g_wsq[kc][m0 + wid * 16 + s * 2 + half] = v;
    }
    if (mt == 0) {
#pragma unroll
        for (int s = 0; s < 4; s++) {
            float v = vsq[s];
#pragma unroll
            for (int o = 1; o < 16; o <<= 1) v += __shfl_xor_sync(0xffffffffu, v, o);
            if (lq == 0) g_vsq[kc][wid * 8 + s * 2 + half] = v;
        }
    }

    // ---- stage D through smem as [b][m] fp32, coalesced store ----
    __syncthreads();
    float* sd = (float*)smem;
#pragma unroll
    for (int ms = 0; ms < 2; ms++)
#pragma unroll
        for (int j = 0; j < 4; j++)
#pragma unroll
            for (int c = 0; c < 4; c++) {
                int ml = wm * 32 + ms * 16 + (lane >> 2) + ((c >> 1) << 3);
                int nn = wn * 32 + j * 8 + (lane & 3) * 2 + (c & 1);
                sd[nn * 128 + ml] = acc[ms][j][c];
            }
    __syncthreads();
#pragma unroll
    for (int i = 0; i < 8; i++) {
        int idx = tid + i * 256;
        int b = idx >> 5, mq = idx & 31;
        *(float4*)&g_vw[kc][b][m0 + mq * 4] = ((const float4*)sd)[idx];
    }
}

// ===========================================================================
// Key-distance GEMM (fp32 SIMT, small)
// ===========================================================================
__global__ __launch_bounds__(256, 2)
void k_kd_gemm(const float* __restrict__ Vp, const float* __restrict__ Wp)
{
    __shared__ __align__(16) float vs[BK][BB];
    __shared__ __align__(16) float ws[BK][BN];

    const int tid = threadIdx.x;
    const int n0 = blockIdx.x * BN;
    const int kc = blockIdx.y;
    const int k0 = kc * KCH_KD;
    const int tx = tid & 31, ty = tid >> 5;
    const int lrow = tid >> 2, lqd = (tid & 3) << 2;

    const float* vsrc  = Vp + (size_t)lrow * FEAT + k0 + lqd;
    const float* wsrc0 = Wp + (size_t)(n0 + lrow) * FEAT + k0 + lqd;
    const float* wsrc1 = wsrc0 + (size_t)64 * FEAT;

    float4 rv = *(const float4*)vsrc;
    float4 rw0 = *(const float4*)wsrc0;
    float4 rw1 = *(const float4*)wsrc1;

    float acc[8][4];
#pragma unroll
    for (int i = 0; i < 8; i++)
#pragma unroll
        for (int j = 0; j < 4; j++) acc[i][j] = 0.f;

    constexpr int STEPS = KCH_KD / BK;
    for (int kt = 0; kt < STEPS; ++kt) {
        __syncthreads();
        vs[lqd + 0][lrow] = rv.x;  vs[lqd + 1][lrow] = rv.y;
        vs[lqd + 2][lrow] = rv.z;  vs[lqd + 3][lrow] = rv.w;
        ws[lqd + 0][lrow] = rw0.x; ws[lqd + 1][lrow] = rw0.y;
        ws[lqd + 2][lrow] = rw0.z; ws[lqd + 3][lrow] = rw0.w;
        ws[lqd + 0][lrow + 64] = rw1.x; ws[lqd + 1][lrow + 64] = rw1.y;
        ws[lqd + 2][lrow + 64] = rw1.z; ws[lqd + 3][lrow + 64] = rw1.w;
        __syncthreads();
        if (kt + 1 < STEPS) {
            rv  = *(const float4*)(vsrc  + (kt + 1) * BK);
            rw0 = *(const float4*)(wsrc0 + (kt + 1) * BK);
            rw1 = *(const float4*)(wsrc1 + (kt + 1) * BK);
        }
#pragma unroll
        for (int kk = 0; kk < BK; ++kk) {
            float a[8], bv[4];
            *(float4*)&a[0] = *(const float4*)&vs[kk][ty * 8];
            *(float4*)&a[4] = *(const float4*)&vs[kk][ty * 8 + 4];
            *(float4*)&bv[0] = *(const float4*)&ws[kk][tx * 4];
#pragma unroll
            for (int i = 0; i < 8; i++)
#pragma unroll
                for (int j = 0; j < 4; j++)
                    acc[i][j] = fmaf(a[i], bv[j], acc[i][j]);
        }
    }
    const int b0 = ty * 8, nn = n0 + tx * 4;
#pragma unroll
    for (int i = 0; i < 8; i++)
        *(float4*)&g_kdp[kc][b0 + i][nn] =
            make_float4(acc[i][0], acc[i][1], acc[i][2], acc[i][3]);
}

// ===========================================================================
__global__ void k_norms(const float* __restrict__ A, const float* __restrict__ Kk)
{
    int warp = (blockIdx.x * blockDim.x + threadIdx.x) >> 5;
    int lane = threadIdx.x & 31;
    if (warp >= BB + MM) return;
    const float* p = (warp < BB) ? (A + (size_t)warp * FEAT)
                                 : (Kk + (size_t)(warp - BB) * FEAT);
    float s = 0.f;
#pragma unroll
    for (int i = 0; i < FEAT / 128; i++) {
        float4 x = *(const float4*)(p + (lane + i * 32) * 4);
        s += x.x * x.x + x.y * x.y + x.z * x.z + x.w * x.w;
    }
#pragma unroll
    for (int o = 16; o; o >>= 1) s += __shfl_xor_sync(0xffffffffu, s, o);
    if (lane == 0) {
        float nrm = fmaxf(sqrtf(s), 1e-8f);
        if (warp < BB) g_anorm[warp] = nrm;
        else           g_knorm[warp - BB] = nrm;
    }
}

// placeholder so the voxel MMA kernel sits at launch #4 for the profiler
__global__ void k_dummy() {}

// per-(b, m-chunk) masked max/min reduction (combine fused in)
__global__ void k_epilogue2()
{
    const int mc = blockIdx.x, b = blockIdx.y;
    const int tid = threadIdx.x;
    const int m = mc * 128 + tid;
    __shared__ float s_hp[128], s_hn[128];
    __shared__ int   s_f[128];

    float vsq = 0.f;
#pragma unroll
    for (int s = 0; s < KS; s++) vsq += g_vsq[s][b];

    float vw = 0.f, wsq = 0.f;
#pragma unroll
    for (int s = 0; s < KS; s++) { vw += g_vw[s][b][m]; wsq += g_wsq[s][m]; }
    float sv = 1.0f - (vsq + wsq - 2.0f * vw) * (1.0f / (float)NVOX);

    float kdp = 0.f;
#pragma unroll
    for (int s = 0; s < KDS; s++) kdp += g_kdp[s][b][m];
    float kd = 1.0f - kdp / (g_anorm[b] * g_knorm[m]);

    float hp = -1e30f, hn = 1e30f;
    int fl = 0;
    if (sv > BETA) { fl |= 1; hp = kd; }
    if (sv < BETA) { fl |= 2; hn = kd; }

    s_hp[tid] = hp; s_hn[tid] = hn; s_f[tid] = fl;
    __syncthreads();
    for (int o = 64; o; o >>= 1) {
        if (tid < o) {
            s_hp[tid] = fmaxf(s_hp[tid], s_hp[tid + o]);
            s_hn[tid] = fminf(s_hn[tid], s_hn[tid + o]);
            s_f[tid] |= s_f[tid + o];
        }
        __syncthreads();
    }
    if (tid == 0) {
        g_hpp[b][mc] = s_hp[0];
        g_hnn[b][mc] = s_hn[0];
        g_ff [b][mc] = s_f[0];
    }
}

__global__ void k_final2(float* __restrict__ out)
{
    __shared__ float sl[BB], sc[BB];
    const int t = threadIdx.x;
    float hp = -1e30f, hn = 1e30f;
    int f = 0;
#pragma unroll
    for (int mc = 0; mc < MT; mc++) {
        hp = fmaxf(hp, g_hpp[t][mc]);
        hn = fminf(hn, g_hnn[t][mc]);
        f |= g_ff[t][mc];
    }
    bool v = (f == 3);
    sl[t] = v ? fmaxf(hp - hn + MARGIN, 0.f) : 0.f;
    sc[t] = v ? 1.f : 0.f;
    __syncthreads();
    for (int o = 32; o; o >>= 1) {
        if (t < o) { sl[t] += sl[t + o]; sc[t] += sc[t + o]; }
        __syncthreads();
    }
    if (t == 0) out[0] = (sc[0] > 0.f) ? (sl[0] / fmaxf(sc[0], 1.f)) : 0.f;
}

// ===========================================================================
extern "C" void kernel_launch(void* const* d_in, const int* in_sizes, int n_in,
                              void* d_out, int out_size)
{
    (void)in_sizes; (void)n_in; (void)out_size;
    const float* anchor = (const float*)d_in[0];   // (64, 512)
    const float* voxels = (const float*)d_in[1];   // (64, 32^3)
    const float* keys   = (const float*)d_in[2];   // (2048, 512)
    const float* vals   = (const float*)d_in[3];   // (2048, 32^3)
    float* out = (float*)d_out;

    cudaFuncSetAttribute(k_voxel_mma, cudaFuncAttributeMaxDynamicSharedMemorySize, SM_TOTAL);

    k_norms<<<(BB + MM + 7) / 8, 256>>>(anchor, keys);       // #1
    k_kd_gemm<<<dim3(MM / BN, KDS), 256>>>(anchor, keys);    // #2
    k_dummy<<<1, 32>>>();                                    // #3
    k_voxel_mma<<<dim3(MT, KS), 256, SM_TOTAL>>>(voxels, vals); // #4 (profiled)
    k_epilogue2<<<dim3(MT, BB), 128>>>();                    // #5
    k_final2<<<1, BB>>>(out);                                // #6
}

// round 6
// speedup vs baseline: 2.9903x; 1.0207x over previous
#include <cuda_runtime.h>
#include <cuda_fp16.h>
#include <cstdint>
#include <math.h>

// ---------------- problem constants ----------------
#define BB    64
#define MM    2048
#define NVOX  32768
#define FEAT  512
#define MARGIN 0.2f
#define BETA   0.8333333f

// voxel GEMM decomposition
#define MT    16          // m tiles of 128
#define KS    16          // split-K chunks
#define KCH   2048        // K per chunk
#define ITERS 32          // iterations of 64-K per chunk
// key-dist GEMM
#define KDS   4
#define KCH_KD 128
#define BN    128
#define BK    16

// ---------------- scratch (device globals) ----------------
__device__ float g_vw [KS][BB][MM];     // 8MB voxel dot partials
__device__ float g_wsq[KS][MM];
__device__ float g_vsqf[BB];
__device__ float g_kdp[KDS][BB][MM];
__device__ float g_anorm[BB];
__device__ float g_knorm[MM];
__device__ float g_hpp[BB][MT];
__device__ float g_hnn[BB][MT];
__device__ int   g_ff [BB][MT];
// precomputed fp16 hi/lo of voxels (B operand) — 4MB each, L2-resident
__device__ __half g_bhi[BB * NVOX];
__device__ __half g_blo[BB * NVOX];

// ---------------- helpers ----------------
__device__ __forceinline__ uint32_t smem_u32(const void* p) {
    uint32_t a;
    asm("{ .reg .u64 t; cvta.to.shared.u64 t, %1; cvt.u32.u64 %0, t; }" : "=r"(a) : "l"(p));
    return a;
}
#define SWZ(off) ((off) ^ (((off) >> 3) & 0x70))

__device__ __forceinline__ void ldsm4(uint32_t* r, uint32_t addr) {
    asm volatile("ldmatrix.sync.aligned.m8n8.x4.shared.b16 {%0,%1,%2,%3}, [%4];"
        : "=r"(r[0]), "=r"(r[1]), "=r"(r[2]), "=r"(r[3]) : "r"(addr));
}
__device__ __forceinline__ void mma16816(float* d, const uint32_t* a, const uint32_t* b) {
    asm volatile("mma.sync.aligned.m16n8k16.row.col.f32.f16.f16.f32 "
        "{%0,%1,%2,%3}, {%4,%5,%6,%7}, {%8,%9}, {%0,%1,%2,%3};"
        : "+f"(d[0]), "+f"(d[1]), "+f"(d[2]), "+f"(d[3])
        : "r"(a[0]), "r"(a[1]), "r"(a[2]), "r"(a[3]), "r"(b[0]), "r"(b[1]));
}
__device__ __forceinline__ void pref_l2(const void* p) {
    asm volatile("prefetch.global.L2 [%0];" :: "l"(p));
}
__device__ __forceinline__ void cpa16(uint32_t dst, const void* src) {
    asm volatile("cp.async.cg.shared.global [%0], [%1], 16;" :: "r"(dst), "l"(src));
}
#define CPA_COMMIT() asm volatile("cp.async.commit_group;" ::: "memory")
#define CPA_WAIT2()  asm volatile("cp.async.wait_group 2;" ::: "memory")

// smem: A fp16 2 x 16KB at 0; B (hi 8KB + lo 8KB) x 4 buffers at 32768
#define SM_B     32768
#define SM_TOTAL 98304

// ===========================================================================
// Prep: voxels fp32 -> fp16 hi/lo global + vsq (exact, once).
// grid = 64 (one row per block), 256 threads.
// ===========================================================================
__global__ void k_prep(const float* __restrict__ vox)
{
    const int r = blockIdx.x, tid = threadIdx.x;
    const float4* src = (const float4*)(vox + (size_t)r * NVOX);
    uint2* hi = (uint2*)(g_bhi + (size_t)r * NVOX);
    uint2* lo = (uint2*)(g_blo + (size_t)r * NVOX);
    float s = 0.f;
    for (int i = tid; i < NVOX / 4; i += 256) {
        float4 x = src[i];
        __half2 h01 = __float22half2_rn(make_float2(x.x, x.y));
        __half2 h23 = __float22half2_rn(make_float2(x.z, x.w));
        float2 f01 = __half22float2(h01);
        float2 f23 = __half22float2(h23);
        __half2 l01 = __float22half2_rn(make_float2(x.x - f01.x, x.y - f01.y));
        __half2 l23 = __float22half2_rn(make_float2(x.z - f23.x, x.w - f23.y));
        hi[i] = make_uint2(*(uint32_t*)&h01, *(uint32_t*)&h23);
        lo[i] = make_uint2(*(uint32_t*)&l01, *(uint32_t*)&l23);
        s = fmaf(x.x, x.x, fmaf(x.y, x.y, fmaf(x.z, x.z, fmaf(x.w, x.w, s))));
    }
    __shared__ float sr[256];
    sr[tid] = s;
    __syncthreads();
    for (int o = 128; o; o >>= 1) {
        if (tid < o) sr[tid] += sr[tid + o];
        __syncthreads();
    }
    if (tid == 0) g_vsqf[r] = sr[0];
}

// ===========================================================================
// Voxel GEMM: D[m(128) x b(64)] via mma.sync fp16 asymmetric 2-split.
// A converted in-loop (LDG reg prefetch); B streamed by cp.async (4-buf ring).
// ===========================================================================
__global__ void __launch_bounds__(256, 2)
k_voxel_mma(const float* __restrict__ vals)
{
    extern __shared__ __align__(1024) char smem[];
    const uint32_t sb = smem_u32(smem);
    const int tid = threadIdx.x;
    const int wid = tid >> 5, lane = tid & 31;
    const int half = lane >> 4, lq = lane & 15;
    const int mt = blockIdx.x, kc = blockIdx.y;
    const int m0 = mt * 128;
    const int k0 = kc * KCH;

    const int wm = wid >> 1, wn = wid & 1;    // warp: 32m x 32n

    const int lrow8 = (lane & 7) + ((lane >> 3) & 1) * 8;
    const uint32_t lcol = (uint32_t)((lane >> 4) * 16);

    uint32_t aRB[2], aXM[2], bRB[2], bXM[2];
#pragma unroll
    for (int ms = 0; ms < 2; ms++) {
        int r = wm * 32 + ms * 16 + lrow8;
        aRB[ms] = sb + r * 128;
        aXM[ms] = (uint32_t)((r & 7) << 4);
    }
#pragma unroll
    for (int p = 0; p < 2; p++) {
        int r = wn * 32 + p * 16 + lrow8;
        bRB[p] = sb + SM_B + r * 128;
        bXM[p] = (uint32_t)((r & 7) << 4);
    }

    // B cp.async per-thread assignment: row = tid>>2, chunk pair (tid&3)*2
    const int brow = tid >> 2;
    const int bc0 = (tid & 3) * 2;
    const uint32_t bd0 = SWZ((uint32_t)(brow * 128 + bc0 * 16));
    const uint32_t bd1 = SWZ((uint32_t)(brow * 128 + (bc0 + 1) * 16));
    const char* bhsrc = (const char*)(g_bhi + (size_t)brow * NVOX + k0) + bc0 * 16;
    const char* blsrc = (const char*)(g_blo + (size_t)brow * NVOX + k0) + bc0 * 16;

    float acc[2][4][4];
#pragma unroll
    for (int i = 0; i < 2; i++)
#pragma unroll
        for (int j = 0; j < 4; j++)
#pragma unroll
            for (int c = 0; c < 4; c++) acc[i][j][c] = 0.f;

    float wsq[8];
#pragma unroll
    for (int s = 0; s < 8; s++) wsq[s] = 0.f;

    const float* aptr = vals + (size_t)m0 * NVOX + k0 + lq * 4;

    // prologue: A iter 0 into regs; B iters 0..2 in flight
    float4 rva[8];
#pragma unroll
    for (int s = 0; s < 8; s++)
        rva[s] = *(const float4*)(aptr + (size_t)(wid * 16 + s * 2 + half) * NVOX);
#pragma unroll
    for (int d = 0; d < 3; d++) {
        uint32_t bb = sb + SM_B + (uint32_t)d * 16384u;
        cpa16(bb + bd0, bhsrc + d * 128);
        cpa16(bb + bd1, bhsrc + d * 128 + 16);
        cpa16(bb + 8192 + bd0, blsrc + d * 128);
        cpa16(bb + 8192 + bd1, blsrc + d * 128 + 16);
        CPA_COMMIT();
    }
#pragma unroll
    for (int s = 0; s < 8; s++)
        pref_l2(aptr + (size_t)(wid * 16 + s * 2 + half) * NVOX + 64);

    for (int it = 0; it < ITERS; ++it) {
        const uint32_t abo = (uint32_t)(it & 1) * 16384u;
        const uint32_t bbo = (uint32_t)(it & 3) * 16384u;

        // ---- A: fp32 -> fp16 (hi only), swizzled store ----
#pragma unroll
        for (int s = 0; s < 8; s++) {
            const int r = wid * 16 + s * 2 + half;
            float4 x = rva[s];
            __half2 h01 = __float22half2_rn(make_float2(x.x, x.y));
            __half2 h23 = __float22half2_rn(make_float2(x.z, x.w));
            wsq[s] = fmaf(x.x, x.x, fmaf(x.y, x.y, fmaf(x.z, x.z, fmaf(x.w, x.w, wsq[s]))));
            uint32_t off = SWZ((uint32_t)(r * 128 + lq * 8));
            *(uint2*)(smem + abo + off) =
                make_uint2(*(uint32_t*)&h01, *(uint32_t*)&h23);
        }

        // next-iter A LDGs before the barrier; L2 prefetch 2 ahead
        if (it + 1 < ITERS) {
            const int kb = (it + 1) * 64;
#pragma unroll
            for (int s = 0; s < 8; s++)
                rva[s] = *(const float4*)(aptr + (size_t)(wid * 16 + s * 2 + half) * NVOX + kb);
        }
        if (it + 2 < ITERS) {
            const int kb2 = (it + 2) * 64;
#pragma unroll
            for (int s = 0; s < 8; s++)
                pref_l2(aptr + (size_t)(wid * 16 + s * 2 + half) * NVOX + kb2);
        }

        CPA_WAIT2();          // B(it) landed (it+1, it+2 still in flight)
        __syncthreads();      // A fp16 + B visible to all warps

        // issue B(it+3) into ring slot (it+3)&3 (disjoint from slot it&3)
        if (it + 3 < ITERS) {
            uint32_t bb = sb + SM_B + (uint32_t)((it + 3) & 3) * 16384u;
            const char* sh = bhsrc + (it + 3) * 128;
            const char* sl = blsrc + (it + 3) * 128;
            cpa16(bb + bd0, sh);
            cpa16(bb + bd1, sh + 16);
            cpa16(bb + 8192 + bd0, sl);
            cpa16(bb + 8192 + bd1, sl + 16);
        }
        CPA_COMMIT();

        // ---- MMA phase: acc += ah*bh + ah*bl ----
#pragma unroll
        for (int kk = 0; kk < 4; kk++) {
            const uint32_t col = (uint32_t)(kk * 32) + lcol;
            uint32_t aH[2][4];
#pragma unroll
            for (int ms = 0; ms < 2; ms++)
                ldsm4(aH[ms], aRB[ms] + abo + (col ^ aXM[ms]));
            uint32_t bH[2][4], bL[2][4];
#pragma unroll
            for (int p = 0; p < 2; p++) {
                uint32_t bd = bRB[p] + bbo + (col ^ bXM[p]);
                ldsm4(bH[p], bd);
                ldsm4(bL[p], bd + 8192);
            }
#pragma unroll
            for (int ms = 0; ms < 2; ms++)
#pragma unroll
                for (int j = 0; j < 4; j++) {
                    const int p = j >> 1, q = j & 1;
                    uint32_t bhf[2] = { bH[p][q], bH[p][q + 2] };
                    uint32_t blf[2] = { bL[p][q], bL[p][q + 2] };
                    mma16816(acc[ms][j], aH[ms], bhf);
                    mma16816(acc[ms][j], aH[ms], blf);
                }
        }
    }

    // ---- wsq partials (reduce 16 lanes sharing a row) ----
#pragma unroll
    for (int s = 0; s < 8; s++) {
        float v = wsq[s];
#pragma unroll
        for (int o = 1; o < 16; o <<= 1) v += __shfl_xor_sync(0xffffffffu, v, o);
        if (lq == 0) g_wsq[kc][m0 + wid * 16 + s * 2 + half] = v;
    }

    // ---- stage D through smem as [b][m] fp32, coalesced store ----
    __syncthreads();
    float* sd = (float*)smem;
#pragma unroll
    for (int ms = 0; ms < 2; ms++)
#pragma unroll
        for (int j = 0; j < 4; j++)
#pragma unroll
            for (int c = 0; c < 4; c++) {
                int ml = wm * 32 + ms * 16 + (lane >> 2) + ((c >> 1) << 3);
                int nn = wn * 32 + j * 8 + (lane & 3) * 2 + (c & 1);
                sd[nn * 128 + ml] = acc[ms][j][c];
            }
    __syncthreads();
#pragma unroll
    for (int i = 0; i < 8; i++) {
        int idx = tid + i * 256;
        int b = idx >> 5, mq = idx & 31;
        *(float4*)&g_vw[kc][b][m0 + mq * 4] = ((const float4*)sd)[idx];
    }
}

// ===========================================================================
// Key-distance GEMM (fp32 SIMT, small)
// ===========================================================================
__global__ __launch_bounds__(256, 2)
void k_kd_gemm(const float* __restrict__ Vp, const float* __restrict__ Wp)
{
    __shared__ __align__(16) float vs[BK][BB];
    __shared__ __align__(16) float ws[BK][BN];

    const int tid = threadIdx.x;
    const int n0 = blockIdx.x * BN;
    const int kc = blockIdx.y;
    const int k0 = kc * KCH_KD;
    const int tx = tid & 31, ty = tid >> 5;
    const int lrow = tid >> 2, lqd = (tid & 3) << 2;

    const float* vsrc  = Vp + (size_t)lrow * FEAT + k0 + lqd;
    const float* wsrc0 = Wp + (size_t)(n0 + lrow) * FEAT + k0 + lqd;
    const float* wsrc1 = wsrc0 + (size_t)64 * FEAT;

    float4 rv = *(const float4*)vsrc;
    float4 rw0 = *(const float4*)wsrc0;
    float4 rw1 = *(const float4*)wsrc1;

    float acc[8][4];
#pragma unroll
    for (int i = 0; i < 8; i++)
#pragma unroll
        for (int j = 0; j < 4; j++) acc[i][j] = 0.f;

    constexpr int STEPS = KCH_KD / BK;
    for (int kt = 0; kt < STEPS; ++kt) {
        __syncthreads();
        vs[lqd + 0][lrow] = rv.x;  vs[lqd + 1][lrow] = rv.y;
        vs[lqd + 2][lrow] = rv.z;  vs[lqd + 3][lrow] = rv.w;
        ws[lqd + 0][lrow] = rw0.x; ws[lqd + 1][lrow] = rw0.y;
        ws[lqd + 2][lrow] = rw0.z; ws[lqd + 3][lrow] = rw0.w;
        ws[lqd + 0][lrow + 64] = rw1.x; ws[lqd + 1][lrow + 64] = rw1.y;
        ws[lqd + 2][lrow + 64] = rw1.z; ws[lqd + 3][lrow + 64] = rw1.w;
        __syncthreads();
        if (kt + 1 < STEPS) {
            rv  = *(const float4*)(vsrc  + (kt + 1) * BK);
            rw0 = *(const float4*)(wsrc0 + (kt + 1) * BK);
            rw1 = *(const float4*)(wsrc1 + (kt + 1) * BK);
        }
#pragma unroll
        for (int kk = 0; kk < BK; ++kk) {
            float a[8], bv[4];
            *(float4*)&a[0] = *(const float4*)&vs[kk][ty * 8];
            *(float4*)&a[4] = *(const float4*)&vs[kk][ty * 8 + 4];
            *(float4*)&bv[0] = *(const float4*)&ws[kk][tx * 4];
#pragma unroll
            for (int i = 0; i < 8; i++)
#pragma unroll
                for (int j = 0; j < 4; j++)
                    acc[i][j] = fmaf(a[i], bv[j], acc[i][j]);
        }
    }
    const int b0 = ty * 8, nn = n0 + tx * 4;
#pragma unroll
    for (int i = 0; i < 8; i++)
        *(float4*)&g_kdp[kc][b0 + i][nn] =
            make_float4(acc[i][0], acc[i][1], acc[i][2], acc[i][3]);
}

// ===========================================================================
__global__ void k_norms(const float* __restrict__ A, const float* __restrict__ Kk)
{
    int warp = (blockIdx.x * blockDim.x + threadIdx.x) >> 5;
    int lane = threadIdx.x & 31;
    if (warp >= BB + MM) return;
    const float* p = (warp < BB) ? (A + (size_t)warp * FEAT)
                                 : (Kk + (size_t)(warp - BB) * FEAT);
    float s = 0.f;
#pragma unroll
    for (int i = 0; i < FEAT / 128; i++) {
        float4 x = *(const float4*)(p + (lane + i * 32) * 4);
        s += x.x * x.x + x.y * x.y + x.z * x.z + x.w * x.w;
    }
#pragma unroll
    for (int o = 16; o; o >>= 1) s += __shfl_xor_sync(0xffffffffu, s, o);
    if (lane == 0) {
        float nrm = fmaxf(sqrtf(s), 1e-8f);
        if (warp < BB) g_anorm[warp] = nrm;
        else           g_knorm[warp - BB] = nrm;
    }
}

// per-(b, m-chunk) masked max/min reduction
__global__ void k_epilogue2()
{
    const int mc = blockIdx.x, b = blockIdx.y;
    const int tid = threadIdx.x;
    const int m = mc * 128 + tid;
    __shared__ float s_hp[128], s_hn[128];
    __shared__ int   s_f[128];

    const float vsq = g_vsqf[b];

    float vw = 0.f, wsq = 0.f;
#pragma unroll
    for (int s = 0; s < KS; s++) { vw += g_vw[s][b][m]; wsq += g_wsq[s][m]; }
    float sv = 1.0f - (vsq + wsq - 2.0f * vw) * (1.0f / (float)NVOX);

    float kdp = 0.f;
#pragma unroll
    for (int s = 0; s < KDS; s++) kdp += g_kdp[s][b][m];
    float kd = 1.0f - kdp / (g_anorm[b] * g_knorm[m]);

    float hp = -1e30f, hn = 1e30f;
    int fl = 0;
    if (sv > BETA) { fl |= 1; hp = kd; }
    if (sv < BETA) { fl |= 2; hn = kd; }

    s_hp[tid] = hp; s_hn[tid] = hn; s_f[tid] = fl;
    __syncthreads();
    for (int o = 64; o; o >>= 1) {
        if (tid < o) {
            s_hp[tid] = fmaxf(s_hp[tid], s_hp[tid + o]);
            s_hn[tid] = fminf(s_hn[tid], s_hn[tid + o]);
            s_f[tid] |= s_f[tid + o];
        }
        __syncthreads();
    }
    if (tid == 0) {
        g_hpp[b][mc] = s_hp[0];
        g_hnn[b][mc] = s_hn[0];
        g_ff [b][mc] = s_f[0];
    }
}

__global__ void k_final2(float* __restrict__ out)
{
    __shared__ float sl[BB], sc[BB];
    const int t = threadIdx.x;
    float hp = -1e30f, hn = 1e30f;
    int f = 0;
#pragma unroll
    for (int mc = 0; mc < MT; mc++) {
        hp = fmaxf(hp, g_hpp[t][mc]);
        hn = fminf(hn, g_hnn[t][mc]);
        f |= g_ff[t][mc];
    }
    bool v = (f == 3);
    sl[t] = v ? fmaxf(hp - hn + MARGIN, 0.f) : 0.f;
    sc[t] = v ? 1.f : 0.f;
    __syncthreads();
    for (int o = 32; o; o >>= 1) {
        if (t < o) { sl[t] += sl[t + o]; sc[t] += sc[t + o]; }
        __syncthreads();
    }
    if (t == 0) out[0] = (sc[0] > 0.f) ? (sl[0] / fmaxf(sc[0], 1.f)) : 0.f;
}

// ===========================================================================
extern "C" void kernel_launch(void* const* d_in, const int* in_sizes, int n_in,
                              void* d_out, int out_size)
{
    (void)in_sizes; (void)n_in; (void)out_size;
    const float* anchor = (const float*)d_in[0];   // (64, 512)
    const float* voxels = (const float*)d_in[1];   // (64, 32^3)
    const float* keys   = (const float*)d_in[2];   // (2048, 512)
    const float* vals   = (const float*)d_in[3];   // (2048, 32^3)
    float* out = (float*)d_out;

    cudaFuncSetAttribute(k_voxel_mma, cudaFuncAttributeMaxDynamicSharedMemorySize, SM_TOTAL);

    k_norms<<<(BB + MM + 7) / 8, 256>>>(anchor, keys);        // #1
    k_kd_gemm<<<dim3(MM / BN, KDS), 256>>>(anchor, keys);     // #2
    k_prep<<<BB, 256>>>(voxels);                              // #3
    k_voxel_mma<<<dim3(MT, KS), 256, SM_TOTAL>>>(vals);       // #4 (profiled)
    k_epilogue2<<<dim3(MT, BB), 128>>>();                     // #5
    k_final2<<<1, BB>>>(out);                                 // #6
}

// round 7
// speedup vs baseline: 3.0678x; 1.0259x over previous
#include <cuda_runtime.h>
#include <cuda_fp16.h>
#include <cstdint>
#include <math.h>

// ---------------- problem constants ----------------
#define BB    64
#define MM    2048
#define NVOX  32768
#define FEAT  512
#define MARGIN 0.2f
#define BETA   0.8333333f

// voxel GEMM decomposition
#define MT    16          // m tiles of 128
#define KS    16          // split-K chunks
#define KCH   2048        // K per chunk
#define ITERS 32          // iterations of 64-K per chunk
// key-dist GEMM
#define KDS   4
#define KCH_KD 128
#define BN    128
#define BK    16

// ---------------- scratch (device globals) ----------------
__device__ float g_vw [KS][BB][MM];     // 8MB voxel dot partials
__device__ float g_wsq[KS][MM];
__device__ float g_vsqp[4][BB];
__device__ float g_kdp[KDS][BB][MM];
__device__ float g_asq[KDS][BB];
__device__ float g_ksq[KDS][MM];
__device__ float g_hpp[BB][MT];
__device__ float g_hnn[BB][MT];
__device__ int   g_ff [BB][MT];
// precomputed fp16 hi/lo of voxels (B operand) — 4MB each, L2-resident
__device__ __half g_bhi[BB * NVOX];
__device__ __half g_blo[BB * NVOX];

// ---------------- helpers ----------------
__device__ __forceinline__ uint32_t smem_u32(const void* p) {
    uint32_t a;
    asm("{ .reg .u64 t; cvta.to.shared.u64 t, %1; cvt.u32.u64 %0, t; }" : "=r"(a) : "l"(p));
    return a;
}
#define SWZ(off) ((off) ^ (((off) >> 3) & 0x70))

__device__ __forceinline__ void ldsm4(uint32_t* r, uint32_t addr) {
    asm volatile("ldmatrix.sync.aligned.m8n8.x4.shared.b16 {%0,%1,%2,%3}, [%4];"
        : "=r"(r[0]), "=r"(r[1]), "=r"(r[2]), "=r"(r[3]) : "r"(addr));
}
__device__ __forceinline__ void mma16816(float* d, const uint32_t* a, const uint32_t* b) {
    asm volatile("mma.sync.aligned.m16n8k16.row.col.f32.f16.f16.f32 "
        "{%0,%1,%2,%3}, {%4,%5,%6,%7}, {%8,%9}, {%0,%1,%2,%3};"
        : "+f"(d[0]), "+f"(d[1]), "+f"(d[2]), "+f"(d[3])
        : "r"(a[0]), "r"(a[1]), "r"(a[2]), "r"(a[3]), "r"(b[0]), "r"(b[1]));
}
__device__ __forceinline__ void pref_l2(const void* p) {
    asm volatile("prefetch.global.L2 [%0];" :: "l"(p));
}
__device__ __forceinline__ void cpa16(uint32_t dst, const void* src) {
    asm volatile("cp.async.cg.shared.global [%0], [%1], 16;" :: "r"(dst), "l"(src));
}
#define CPA_COMMIT() asm volatile("cp.async.commit_group;" ::: "memory")
#define CPA_WAIT2()  asm volatile("cp.async.wait_group 2;" ::: "memory")

// smem: A fp16 2 x 16KB at 0; B (hi 8KB + lo 8KB) x 4 buffers at 32768
#define SM_B     32768
#define SM_TOTAL 98304

// ===========================================================================
// Prep: voxels fp32 -> fp16 hi/lo global + vsq partials. grid = 256.
// ===========================================================================
__global__ void k_prep(const float* __restrict__ vox)
{
    const int r = blockIdx.x >> 2, ch = blockIdx.x & 3, tid = threadIdx.x;
    const size_t base = (size_t)r * NVOX + (size_t)ch * (NVOX / 4);
    const float4* src = (const float4*)(vox + base);
    uint2* hi = (uint2*)(g_bhi + base);
    uint2* lo = (uint2*)(g_blo + base);
    float s = 0.f;
    for (int i = tid; i < NVOX / 16; i += 256) {
        float4 x = src[i];
        __half2 h01 = __float22half2_rn(make_float2(x.x, x.y));
        __half2 h23 = __float22half2_rn(make_float2(x.z, x.w));
        float2 f01 = __half22float2(h01);
        float2 f23 = __half22float2(h23);
        __half2 l01 = __float22half2_rn(make_float2(x.x - f01.x, x.y - f01.y));
        __half2 l23 = __float22half2_rn(make_float2(x.z - f23.x, x.w - f23.y));
        hi[i] = make_uint2(*(uint32_t*)&h01, *(uint32_t*)&h23);
        lo[i] = make_uint2(*(uint32_t*)&l01, *(uint32_t*)&l23);
        s = fmaf(x.x, x.x, fmaf(x.y, x.y, fmaf(x.z, x.z, fmaf(x.w, x.w, s))));
    }
    __shared__ float sr[256];
    sr[tid] = s;
    __syncthreads();
    for (int o = 128; o; o >>= 1) {
        if (tid < o) sr[tid] += sr[tid + o];
        __syncthreads();
    }
    if (tid == 0) g_vsqp[ch][r] = sr[0];
}

// ===========================================================================
// Voxel GEMM: fp16 asymmetric 2-split, software-pipelined:
// iter it runs MMA(it) interleaved with convert(it+1).
// ===========================================================================
__global__ void __launch_bounds__(256, 2)
k_voxel_mma(const float* __restrict__ vals)
{
    extern __shared__ __align__(1024) char smem[];
    const uint32_t sb = smem_u32(smem);
    const int tid = threadIdx.x;
    const int wid = tid >> 5, lane = tid & 31;
    const int half = lane >> 4, lq = lane & 15;
    const int mt = blockIdx.x, kc = blockIdx.y;
    const int m0 = mt * 128;
    const int k0 = kc * KCH;

    const int wm = wid >> 1, wn = wid & 1;    // warp: 32m x 32n

    const int lrow8 = (lane & 7) + ((lane >> 3) & 1) * 8;
    const uint32_t lcol = (uint32_t)((lane >> 4) * 16);

    uint32_t aRB[2], aXM[2], bRB[2], bXM[2];
#pragma unroll
    for (int ms = 0; ms < 2; ms++) {
        int r = wm * 32 + ms * 16 + lrow8;
        aRB[ms] = sb + r * 128;
        aXM[ms] = (uint32_t)((r & 7) << 4);
    }
#pragma unroll
    for (int p = 0; p < 2; p++) {
        int r = wn * 32 + p * 16 + lrow8;
        bRB[p] = sb + SM_B + r * 128;
        bXM[p] = (uint32_t)((r & 7) << 4);
    }

    // B cp.async per-thread assignment
    const int brow = tid >> 2;
    const int bc0 = (tid & 3) * 2;
    const uint32_t bd0 = SWZ((uint32_t)(brow * 128 + bc0 * 16));
    const uint32_t bd1 = SWZ((uint32_t)(brow * 128 + (bc0 + 1) * 16));
    const char* bhsrc = (const char*)(g_bhi + (size_t)brow * NVOX + k0) + bc0 * 16;
    const char* blsrc = (const char*)(g_blo + (size_t)brow * NVOX + k0) + bc0 * 16;

    float acc[2][4][4];
#pragma unroll
    for (int i = 0; i < 2; i++)
#pragma unroll
        for (int j = 0; j < 4; j++)
#pragma unroll
            for (int c = 0; c < 4; c++) acc[i][j][c] = 0.f;

    float wsq[8];
#pragma unroll
    for (int s = 0; s < 8; s++) wsq[s] = 0.f;

    const float* aptr = vals + (size_t)m0 * NVOX + k0 + lq * 4;

    // ---- prologue ----
    float4 rva[8];
#pragma unroll
    for (int s = 0; s < 8; s++)
        rva[s] = *(const float4*)(aptr + (size_t)(wid * 16 + s * 2 + half) * NVOX);
#pragma unroll
    for (int d = 0; d < 3; d++) {
        uint32_t bb = sb + SM_B + (uint32_t)d * 16384u;
        cpa16(bb + bd0, bhsrc + d * 128);
        cpa16(bb + bd1, bhsrc + d * 128 + 16);
        cpa16(bb + 8192 + bd0, blsrc + d * 128);
        cpa16(bb + 8192 + bd1, blsrc + d * 128 + 16);
        CPA_COMMIT();
    }
#pragma unroll
    for (int s = 0; s < 8; s++)
        pref_l2(aptr + (size_t)(wid * 16 + s * 2 + half) * NVOX + 64);

    // convert A(0) -> buf0
#pragma unroll
    for (int s = 0; s < 8; s++) {
        const int r = wid * 16 + s * 2 + half;
        float4 x = rva[s];
        __half2 h01 = __float22half2_rn(make_float2(x.x, x.y));
        __half2 h23 = __float22half2_rn(make_float2(x.z, x.w));
        wsq[s] = fmaf(x.x, x.x, fmaf(x.y, x.y, fmaf(x.z, x.z, fmaf(x.w, x.w, wsq[s]))));
        uint32_t off = SWZ((uint32_t)(r * 128 + lq * 8));
        *(uint2*)(smem + off) = make_uint2(*(uint32_t*)&h01, *(uint32_t*)&h23);
    }
    // load A(1)
#pragma unroll
    for (int s = 0; s < 8; s++)
        rva[s] = *(const float4*)(aptr + (size_t)(wid * 16 + s * 2 + half) * NVOX + 64);
#pragma unroll
    for (int s = 0; s < 8; s++)
        pref_l2(aptr + (size_t)(wid * 16 + s * 2 + half) * NVOX + 128);

    CPA_WAIT2();          // B(0) landed
    __syncthreads();

    // ---- main loop: MMA(it) interleaved with convert(it+1) ----
    for (int it = 0; it < ITERS - 1; ++it) {
        const uint32_t abo_m = (uint32_t)(it & 1) * 16384u;
        const uint32_t abo_c = (uint32_t)((it + 1) & 1) * 16384u;
        const uint32_t bbo   = (uint32_t)(it & 3) * 16384u;

        // issue B(it+3) into ring slot (safe: slot read finished at it-1)
        if (it + 3 < ITERS) {
            uint32_t bb = sb + SM_B + (uint32_t)((it + 3) & 3) * 16384u;
            const char* sh = bhsrc + (it + 3) * 128;
            const char* sl = blsrc + (it + 3) * 128;
            cpa16(bb + bd0, sh);
            cpa16(bb + bd1, sh + 16);
            cpa16(bb + 8192 + bd0, sl);
            cpa16(bb + 8192 + bd1, sl + 16);
        }
        CPA_COMMIT();

        // interleaved: 4 kk-blocks of {ldsm + 16 mma + 2 convert steps}
#pragma unroll
        for (int kk = 0; kk < 4; kk++) {
            const uint32_t col = (uint32_t)(kk * 32) + lcol;
            uint32_t aH[2][4];
#pragma unroll
            for (int ms = 0; ms < 2; ms++)
                ldsm4(aH[ms], aRB[ms] + abo_m + (col ^ aXM[ms]));
            uint32_t bH[2][4], bL[2][4];
#pragma unroll
            for (int p = 0; p < 2; p++) {
                uint32_t bd = bRB[p] + bbo + (col ^ bXM[p]);
                ldsm4(bH[p], bd);
                ldsm4(bL[p], bd + 8192);
            }
            // convert 2 A rows-pairs for iter it+1 (writes other A buffer)
#pragma unroll
            for (int s = kk * 2; s < kk * 2 + 2; s++) {
                const int r = wid * 16 + s * 2 + half;
                float4 x = rva[s];
                __half2 h01 = __float22half2_rn(make_float2(x.x, x.y));
                __half2 h23 = __float22half2_rn(make_float2(x.z, x.w));
                wsq[s] = fmaf(x.x, x.x, fmaf(x.y, x.y, fmaf(x.z, x.z, fmaf(x.w, x.w, wsq[s]))));
                uint32_t off = SWZ((uint32_t)(r * 128 + lq * 8));
                *(uint2*)(smem + abo_c + off) =
                    make_uint2(*(uint32_t*)&h01, *(uint32_t*)&h23);
            }
#pragma unroll
            for (int ms = 0; ms < 2; ms++)
#pragma unroll
                for (int j = 0; j < 4; j++) {
                    const int p = j >> 1, q = j & 1;
                    uint32_t bhf[2] = { bH[p][q], bH[p][q + 2] };
                    uint32_t blf[2] = { bL[p][q], bL[p][q + 2] };
                    mma16816(acc[ms][j], aH[ms], bhf);
                    mma16816(acc[ms][j], aH[ms], blf);
                }
        }

        // A loads for it+2; L2 prefetch it+3
        if (it + 2 < ITERS) {
            const int kb = (it + 2) * 64;
#pragma unroll
            for (int s = 0; s < 8; s++)
                rva[s] = *(const float4*)(aptr + (size_t)(wid * 16 + s * 2 + half) * NVOX + kb);
        }
        if (it + 3 < ITERS) {
            const int kb2 = (it + 3) * 64;
#pragma unroll
            for (int s = 0; s < 8; s++)
                pref_l2(aptr + (size_t)(wid * 16 + s * 2 + half) * NVOX + kb2);
        }

        CPA_WAIT2();          // B(it+1) landed
        __syncthreads();
    }

    // ---- final MMA (it = ITERS-1), no convert ----
    {
        const uint32_t abo_m = (uint32_t)((ITERS - 1) & 1) * 16384u;
        const uint32_t bbo   = (uint32_t)((ITERS - 1) & 3) * 16384u;
#pragma unroll
        for (int kk = 0; kk < 4; kk++) {
            const uint32_t col = (uint32_t)(kk * 32) + lcol;
            uint32_t aH[2][4];
#pragma unroll
            for (int ms = 0; ms < 2; ms++)
                ldsm4(aH[ms], aRB[ms] + abo_m + (col ^ aXM[ms]));
            uint32_t bH[2][4], bL[2][4];
#pragma unroll
            for (int p = 0; p < 2; p++) {
                uint32_t bd = bRB[p] + bbo + (col ^ bXM[p]);
                ldsm4(bH[p], bd);
                ldsm4(bL[p], bd + 8192);
            }
#pragma unroll
            for (int ms = 0; ms < 2; ms++)
#pragma unroll
                for (int j = 0; j < 4; j++) {
                    const int p = j >> 1, q = j & 1;
                    uint32_t bhf[2] = { bH[p][q], bH[p][q + 2] };
                    uint32_t blf[2] = { bL[p][q], bL[p][q + 2] };
                    mma16816(acc[ms][j], aH[ms], bhf);
                    mma16816(acc[ms][j], aH[ms], blf);
                }
        }
    }

    // ---- wsq partials (reduce 16 lanes sharing a row) ----
#pragma unroll
    for (int s = 0; s < 8; s++) {
        float v = wsq[s];
#pragma unroll
        for (int o = 1; o < 16; o <<= 1) v += __shfl_xor_sync(0xffffffffu, v, o);
        if (lq == 0) g_wsq[kc][m0 + wid * 16 + s * 2 + half] = v;
    }

    // ---- stage D through smem as [b][m] fp32, coalesced store ----
    __syncthreads();
    float* sd = (float*)smem;
#pragma unroll
    for (int ms = 0; ms < 2; ms++)
#pragma unroll
        for (int j = 0; j < 4; j++)
#pragma unroll
            for (int c = 0; c < 4; c++) {
                int ml = wm * 32 + ms * 16 + (lane >> 2) + ((c >> 1) << 3);
                int nn = wn * 32 + j * 8 + (lane & 3) * 2 + (c & 1);
                sd[nn * 128 + ml] = acc[ms][j][c];
            }
    __syncthreads();
#pragma unroll
    for (int i = 0; i < 8; i++) {
        int idx = tid + i * 256;
        int b = idx >> 5, mq = idx & 31;
        *(float4*)&g_vw[kc][b][m0 + mq * 4] = ((const float4*)sd)[idx];
    }
}

// ===========================================================================
// Key-distance GEMM (fp32 SIMT) + fused square-norm partials
// ===========================================================================
__global__ __launch_bounds__(256, 2)
void k_kd_gemm(const float* __restrict__ Vp, const float* __restrict__ Wp)
{
    __shared__ __align__(16) float vs[BK][BB];
    __shared__ __align__(16) float ws[BK][BN];

    const int tid = threadIdx.x;
    const int n0 = blockIdx.x * BN;
    const int kc = blockIdx.y;
    const int k0 = kc * KCH_KD;
    const int tx = tid & 31, ty = tid >> 5;
    const int lrow = tid >> 2, lqd = (tid & 3) << 2;

    const float* vsrc  = Vp + (size_t)lrow * FEAT + k0 + lqd;
    const float* wsrc0 = Wp + (size_t)(n0 + lrow) * FEAT + k0 + lqd;
    const float* wsrc1 = wsrc0 + (size_t)64 * FEAT;

    float4 rv = *(const float4*)vsrc;
    float4 rw0 = *(const float4*)wsrc0;
    float4 rw1 = *(const float4*)wsrc1;

    float acc[8][4];
#pragma unroll
    for (int i = 0; i < 8; i++)
#pragma unroll
        for (int j = 0; j < 4; j++) acc[i][j] = 0.f;

    float sqv = 0.f, sqw0 = 0.f, sqw1 = 0.f;

    constexpr int STEPS = KCH_KD / BK;
    for (int kt = 0; kt < STEPS; ++kt) {
        __syncthreads();
        vs[lqd + 0][lrow] = rv.x;  vs[lqd + 1][lrow] = rv.y;
        vs[lqd + 2][lrow] = rv.z;  vs[lqd + 3][lrow] = rv.w;
        ws[lqd + 0][lrow] = rw0.x; ws[lqd + 1][lrow] = rw0.y;
        ws[lqd + 2][lrow] = rw0.z; ws[lqd + 3][lrow] = rw0.w;
        ws[lqd + 0][lrow + 64] = rw1.x; ws[lqd + 1][lrow + 64] = rw1.y;
        ws[lqd + 2][lrow + 64] = rw1.z; ws[lqd + 3][lrow + 64] = rw1.w;
        sqv  += rv.x * rv.x + rv.y * rv.y + rv.z * rv.z + rv.w * rv.w;
        sqw0 += rw0.x * rw0.x + rw0.y * rw0.y + rw0.z * rw0.z + rw0.w * rw0.w;
        sqw1 += rw1.x * rw1.x + rw1.y * rw1.y + rw1.z * rw1.z + rw1.w * rw1.w;
        __syncthreads();
        if (kt + 1 < STEPS) {
            rv  = *(const float4*)(vsrc  + (kt + 1) * BK);
            rw0 = *(const float4*)(wsrc0 + (kt + 1) * BK);
            rw1 = *(const float4*)(wsrc1 + (kt + 1) * BK);
        }
#pragma unroll
        for (int kk = 0; kk < BK; ++kk) {
            float a[8], bv[4];
            *(float4*)&a[0] = *(const float4*)&vs[kk][ty * 8];
            *(float4*)&a[4] = *(const float4*)&vs[kk][ty * 8 + 4];
            *(float4*)&bv[0] = *(const float4*)&ws[kk][tx * 4];
#pragma unroll
            for (int i = 0; i < 8; i++)
#pragma unroll
                for (int j = 0; j < 4; j++)
                    acc[i][j] = fmaf(a[i], bv[j], acc[i][j]);
        }
    }
    const int b0 = ty * 8, nn = n0 + tx * 4;
#pragma unroll
    for (int i = 0; i < 8; i++)
        *(float4*)&g_kdp[kc][b0 + i][nn] =
            make_float4(acc[i][0], acc[i][1], acc[i][2], acc[i][3]);

    // reduce 4 quad-threads sharing a row (consecutive lanes)
    sqw0 += __shfl_xor_sync(0xffffffffu, sqw0, 1);
    sqw0 += __shfl_xor_sync(0xffffffffu, sqw0, 2);
    sqw1 += __shfl_xor_sync(0xffffffffu, sqw1, 1);
    sqw1 += __shfl_xor_sync(0xffffffffu, sqw1, 2);
    sqv  += __shfl_xor_sync(0xffffffffu, sqv, 1);
    sqv  += __shfl_xor_sync(0xffffffffu, sqv, 2);
    if ((tid & 3) == 0) {
        g_ksq[kc][n0 + lrow]      = sqw0;
        g_ksq[kc][n0 + 64 + lrow] = sqw1;
        if (blockIdx.x == 0) g_asq[kc][lrow] = sqv;
    }
}

// placeholder to keep k_voxel_mma at launch #4 for the profiler
__global__ void k_dummy() {}

// per-(b, m-chunk) masked max/min reduction
__global__ void k_epilogue2()
{
    const int mc = blockIdx.x, b = blockIdx.y;
    const int tid = threadIdx.x;
    const int m = mc * 128 + tid;
    __shared__ float s_hp[128], s_hn[128];
    __shared__ int   s_f[128];

    const float vsq = g_vsqp[0][b] + g_vsqp[1][b] + g_vsqp[2][b] + g_vsqp[3][b];

    float vw = 0.f, wsq = 0.f;
#pragma unroll
    for (int s = 0; s < KS; s++) { vw += g_vw[s][b][m]; wsq += g_wsq[s][m]; }
    float sv = 1.0f - (vsq + wsq - 2.0f * vw) * (1.0f / (float)NVOX);

    float kdp = 0.f, asq = 0.f, ksq = 0.f;
#pragma unroll
    for (int s = 0; s < KDS; s++) {
        kdp += g_kdp[s][b][m];
        asq += g_asq[s][b];
        ksq += g_ksq[s][m];
    }
    float an = fmaxf(sqrtf(asq), 1e-8f);
    float kn = fmaxf(sqrtf(ksq), 1e-8f);
    float kd = 1.0f - kdp / (an * kn);

    float hp = -1e30f, hn = 1e30f;
    int fl = 0;
    if (sv > BETA) { fl |= 1; hp = kd; }
    if (sv < BETA) { fl |= 2; hn = kd; }

    s_hp[tid] = hp; s_hn[tid] = hn; s_f[tid] = fl;
    __syncthreads();
    for (int o = 64; o; o >>= 1) {
        if (tid < o) {
            s_hp[tid] = fmaxf(s_hp[tid], s_hp[tid + o]);
            s_hn[tid] = fminf(s_hn[tid], s_hn[tid + o]);
            s_f[tid] |= s_f[tid + o];
        }
        __syncthreads();
    }
    if (tid == 0) {
        g_hpp[b][mc] = s_hp[0];
        g_hnn[b][mc] = s_hn[0];
        g_ff [b][mc] = s_f[0];
    }
}

__global__ void k_final2(float* __restrict__ out)
{
    __shared__ float sl[BB], sc[BB];
    const int t = threadIdx.x;
    float hp = -1e30f, hn = 1e30f;
    int f = 0;
#pragma unroll
    for (int mc = 0; mc < MT; mc++) {
        hp = fmaxf(hp, g_hpp[t][mc]);
        hn = fminf(hn, g_hnn[t][mc]);
        f |= g_ff[t][mc];
    }
    bool v = (f == 3);
    sl[t] = v ? fmaxf(hp - hn + MARGIN, 0.f) : 0.f;
    sc[t] = v ? 1.f : 0.f;
    __syncthreads();
    for (int o = 32; o; o >>= 1) {
        if (t < o) { sl[t] += sl[t + o]; sc[t] += sc[t + o]; }
        __syncthreads();
    }
    if (t == 0) out[0] = (sc[0] > 0.f) ? (sl[0] / fmaxf(sc[0], 1.f)) : 0.f;
}

// ===========================================================================
extern "C" void kernel_launch(void* const* d_in, const int* in_sizes, int n_in,
                              void* d_out, int out_size)
{
    (void)in_sizes; (void)n_in; (void)out_size;
    const float* anchor = (const float*)d_in[0];   // (64, 512)
    const float* voxels = (const float*)d_in[1];   // (64, 32^3)
    const float* keys   = (const float*)d_in[2];   // (2048, 512)
    const float* vals   = (const float*)d_in[3];   // (2048, 32^3)
    float* out = (float*)d_out;

    cudaFuncSetAttribute(k_voxel_mma, cudaFuncAttributeMaxDynamicSharedMemorySize, SM_TOTAL);

    k_dummy<<<1, 32>>>();                                     // #1
    k_kd_gemm<<<dim3(MM / BN, KDS), 256>>>(anchor, keys);     // #2
    k_prep<<<256, 256>>>(voxels);                             // #3
    k_voxel_mma<<<dim3(MT, KS), 256, SM_TOTAL>>>(vals);       // #4 (profiled)
    k_epilogue2<<<dim3(MT, BB), 128>>>();                     // #5
    k_final2<<<1, BB>>>(out);                                 // #6
}